// round 5
// baseline (speedup 1.0000x reference)
#include <cuda_runtime.h>

#define NN 100000
#define NE 1600000
#define FD 64
#define NG 64
#define EPSV 1e-5f

// -------- scratch (device globals: no allocation allowed) --------
__device__ float g_deg[NN];         // weighted in-degree
__device__ int   g_cntI[NN];        // integer in-degree
__device__ int   g_ptr[NN + 1];     // CSR row pointers (by dst)
__device__ int   g_fill[NN];        // running fill cursors
__device__ int   g_csrc[NE];        // CSR: src node per slot
__device__ float g_cnrm[NE];        // CSR: norm per slot
__device__ float g_h1[NN * FD];
__device__ float g_h2[NN * FD];
__device__ float g_h3[NN * FD];
__device__ float g_out[NN * FD];
__device__ float g_sum[NG * FD];
__device__ float g_sq[NG * FD];
__device__ float g_cnt[NG];
__device__ float g_psum[NG * FD];
__device__ float g_pmax[NG * FD];   // values >= 0 so uint order == float order
__device__ float g_mc[NG * FD];     // mean * mean_scale
__device__ float g_inv[NG * FD];    // gn_weight * rsqrt(var + eps)

// -------- zero scratch --------
__global__ void k_zero() {
    int i = blockIdx.x * blockDim.x + threadIdx.x;
    if (i < NN) { g_deg[i] = 0.f; g_cntI[i] = 0; }
    if (i < NG * FD) { g_sum[i] = 0.f; g_sq[i] = 0.f; g_psum[i] = 0.f; g_pmax[i] = 0.f; }
    if (i < NG) g_cnt[i] = 0.f;
}

// -------- degree: weighted + integer count --------
__global__ void k_deg(const int* __restrict__ dst, const float* __restrict__ ew) {
    int e = blockIdx.x * blockDim.x + threadIdx.x;
    if (e >= NE) return;
    int d = dst[e];
    atomicAdd(&g_deg[d], ew[e]);
    atomicAdd(&g_cntI[d], 1);
}

// -------- exclusive prefix scan over g_cntI -> g_ptr / g_fill (single block) --------
__global__ void k_scan() {
    __shared__ int sp[1024];
    const int T = 1024;
    const int CH = (NN + T - 1) / T;       // 98
    int t = threadIdx.x;
    int lo = t * CH, hi = min(lo + CH, NN);
    int s = 0;
    for (int i = lo; i < hi; i++) s += g_cntI[i];
    sp[t] = s;
    __syncthreads();
    // Hillis-Steele inclusive scan
    for (int off = 1; off < T; off <<= 1) {
        int v = (t >= off) ? sp[t - off] : 0;
        __syncthreads();
        sp[t] += v;
        __syncthreads();
    }
    int run = sp[t] - s;                   // exclusive offset for this chunk
    for (int i = lo; i < hi; i++) {
        g_ptr[i] = run;
        g_fill[i] = run;
        run += g_cntI[i];
    }
    if (t == T - 1) g_ptr[NN] = NE;
}

// -------- build CSR slots: csrc/cnrm permuted by dst (folds norm computation) --------
__global__ void k_build(const int* __restrict__ src, const int* __restrict__ dst,
                        const float* __restrict__ ew) {
    int e = blockIdx.x * blockDim.x + threadIdx.x;
    if (e >= NE) return;
    int s = src[e], d = dst[e];
    float ds = g_deg[s], dd = g_deg[d];
    float a = (ds > 0.f) ? rsqrtf(ds) : 0.f;
    float c = (dd > 0.f) ? rsqrtf(dd) : 0.f;
    float nrm = a * ew[e] * c;
    int pos = atomicAdd(&g_fill[d], 1);
    g_csrc[pos] = s;
    g_cnrm[pos] = nrm;
}

// -------- gather hop: hout[n] = sum_{e in row n} norm[e] * hin[src[e]] --------
__device__ __forceinline__ void hop_body(const float* __restrict__ hin,
                                         float* __restrict__ hout) {
    unsigned tid = blockIdx.x * blockDim.x + threadIdx.x;
    unsigned node = tid >> 4;
    if (node >= NN) return;
    int c = (tid & 15) * 4;
    int beg = g_ptr[node];
    int end = g_ptr[node + 1];
    float4 acc = {0.f, 0.f, 0.f, 0.f};
    int i = beg;
    for (; i + 2 <= end; i += 2) {
        int   s0 = __ldg(&g_csrc[i]);
        int   s1 = __ldg(&g_csrc[i + 1]);
        float w0 = __ldg(&g_cnrm[i]);
        float w1 = __ldg(&g_cnrm[i + 1]);
        float4 v0 = __ldg((const float4*)(hin + (size_t)s0 * FD + c));
        float4 v1 = __ldg((const float4*)(hin + (size_t)s1 * FD + c));
        acc.x += w0 * v0.x + w1 * v1.x;
        acc.y += w0 * v0.y + w1 * v1.y;
        acc.z += w0 * v0.z + w1 * v1.z;
        acc.w += w0 * v0.w + w1 * v1.w;
    }
    if (i < end) {
        int   s0 = __ldg(&g_csrc[i]);
        float w0 = __ldg(&g_cnrm[i]);
        float4 v0 = __ldg((const float4*)(hin + (size_t)s0 * FD + c));
        acc.x += w0 * v0.x;
        acc.y += w0 * v0.y;
        acc.z += w0 * v0.z;
        acc.w += w0 * v0.w;
    }
    *(float4*)(hout + (size_t)node * FD + c) = acc;
}

__global__ void k_hop1(const float* __restrict__ x) { hop_body(x, g_h1); }
__global__ void k_hop2() { hop_body(g_h1, g_h2); }
__global__ void k_hop3() { hop_body(g_h2, g_h3); }

// -------- out = x@W0 + h1@W1 + h2@W2 + h3@W3 + b --------
__global__ void k_gemm(const float* __restrict__ x, const float* __restrict__ W,
                       const float* __restrict__ b) {
    __shared__ float Ws[FD * FD];
    int grp = threadIdx.x >> 4;
    int j   = threadIdx.x & 15;
    int node0 = blockIdx.x * 64 + grp * 4;

    float4 acc0 = {0,0,0,0}, acc1 = {0,0,0,0}, acc2 = {0,0,0,0}, acc3 = {0,0,0,0};

    int n0 = min(node0 + 0, NN - 1);
    int n1 = min(node0 + 1, NN - 1);
    int n2 = min(node0 + 2, NN - 1);
    int n3 = min(node0 + 3, NN - 1);

    const float* hs[4] = { x, g_h1, g_h2, g_h3 };

    for (int k = 0; k < 4; k++) {
        for (int t = threadIdx.x; t < FD * FD; t += 256) Ws[t] = W[k * FD * FD + t];
        __syncthreads();
        const float* __restrict__ h = hs[k];
        #pragma unroll
        for (int i = 0; i < FD; i += 4) {
            float4 w0 = *(const float4*)&Ws[(i + 0) * FD + j * 4];
            float4 w1 = *(const float4*)&Ws[(i + 1) * FD + j * 4];
            float4 w2 = *(const float4*)&Ws[(i + 2) * FD + j * 4];
            float4 w3 = *(const float4*)&Ws[(i + 3) * FD + j * 4];
            float4 h0 = *(const float4*)&h[n0 * FD + i];
            float4 h1 = *(const float4*)&h[n1 * FD + i];
            float4 h2 = *(const float4*)&h[n2 * FD + i];
            float4 h3 = *(const float4*)&h[n3 * FD + i];
            acc0.x += h0.x*w0.x + h0.y*w1.x + h0.z*w2.x + h0.w*w3.x;
            acc0.y += h0.x*w0.y + h0.y*w1.y + h0.z*w2.y + h0.w*w3.y;
            acc0.z += h0.x*w0.z + h0.y*w1.z + h0.z*w2.z + h0.w*w3.z;
            acc0.w += h0.x*w0.w + h0.y*w1.w + h0.z*w2.w + h0.w*w3.w;
            acc1.x += h1.x*w0.x + h1.y*w1.x + h1.z*w2.x + h1.w*w3.x;
            acc1.y += h1.x*w0.y + h1.y*w1.y + h1.z*w2.y + h1.w*w3.y;
            acc1.z += h1.x*w0.z + h1.y*w1.z + h1.z*w2.z + h1.w*w3.z;
            acc1.w += h1.x*w0.w + h1.y*w1.w + h1.z*w2.w + h1.w*w3.w;
            acc2.x += h2.x*w0.x + h2.y*w1.x + h2.z*w2.x + h2.w*w3.x;
            acc2.y += h2.x*w0.y + h2.y*w1.y + h2.z*w2.y + h2.w*w3.y;
            acc2.z += h2.x*w0.z + h2.y*w1.z + h2.z*w2.z + h2.w*w3.z;
            acc2.w += h2.x*w0.w + h2.y*w1.w + h2.z*w2.w + h2.w*w3.w;
            acc3.x += h3.x*w0.x + h3.y*w1.x + h3.z*w2.x + h3.w*w3.x;
            acc3.y += h3.x*w0.y + h3.y*w1.y + h3.z*w2.y + h3.w*w3.y;
            acc3.z += h3.x*w0.z + h3.y*w1.z + h3.z*w2.z + h3.w*w3.z;
            acc3.w += h3.x*w0.w + h3.y*w1.w + h3.z*w2.w + h3.w*w3.w;
        }
        __syncthreads();
    }

    float4 bv = *(const float4*)&b[j * 4];
    acc0.x += bv.x; acc0.y += bv.y; acc0.z += bv.z; acc0.w += bv.w;
    acc1.x += bv.x; acc1.y += bv.y; acc1.z += bv.z; acc1.w += bv.w;
    acc2.x += bv.x; acc2.y += bv.y; acc2.z += bv.z; acc2.w += bv.w;
    acc3.x += bv.x; acc3.y += bv.y; acc3.z += bv.z; acc3.w += bv.w;

    if (node0 + 0 < NN) *(float4*)&g_out[(node0 + 0) * FD + j * 4] = acc0;
    if (node0 + 1 < NN) *(float4*)&g_out[(node0 + 1) * FD + j * 4] = acc1;
    if (node0 + 2 < NN) *(float4*)&g_out[(node0 + 2) * FD + j * 4] = acc2;
    if (node0 + 3 < NN) *(float4*)&g_out[(node0 + 3) * FD + j * 4] = acc3;
}

// -------- per-graph sum / sumsq / count over g_out (batch sorted) --------
__global__ void k_stats(const int* __restrict__ batch) {
    int f    = threadIdx.x & 63;
    int lane = threadIdx.x >> 6;   // 0..3
    int base = blockIdx.x * 128;
    float s = 0.f, q = 0.f, c = 0.f;
    int cur = -1;
    for (int t = 0; t < 32; t++) {
        int n = base + t * 4 + lane;
        if (n >= NN) break;
        int g = batch[n];
        if (g != cur) {
            if (cur >= 0) {
                atomicAdd(&g_sum[cur * FD + f], s);
                atomicAdd(&g_sq[cur * FD + f], q);
                if (f == 0) atomicAdd(&g_cnt[cur], c);
            }
            cur = g; s = 0.f; q = 0.f; c = 0.f;
        }
        float v = g_out[n * FD + f];
        s += v; q += v * v; c += 1.f;
    }
    if (cur >= 0) {
        atomicAdd(&g_sum[cur * FD + f], s);
        atomicAdd(&g_sq[cur * FD + f], q);
        if (f == 0) atomicAdd(&g_cnt[cur], c);
    }
}

// -------- mean/var -> premultiplied center & inv-std --------
__global__ void k_meanvar(const float* __restrict__ gnw, const float* __restrict__ ms) {
    int i = blockIdx.x * blockDim.x + threadIdx.x;
    if (i >= NG * FD) return;
    int g = i >> 6, f = i & 63;
    float cnt  = fmaxf(g_cnt[g], 1.f);
    float mean = g_sum[i] / cnt;
    float m    = ms[f];
    float var = g_sq[i] / cnt - 2.f * m * mean * mean + m * m * mean * mean;
    g_mc[i]  = mean * m;
    g_inv[i] = gnw[f] * rsqrtf(var + EPSV);
}

// -------- final: h_emb = relu(gn(out) + x), accumulate pool sum/max --------
__global__ void k_final(const float* __restrict__ x, const int* __restrict__ batch,
                        const float* __restrict__ gnb, float* __restrict__ out) {
    int f    = threadIdx.x & 63;
    int lane = threadIdx.x >> 6;
    int base = blockIdx.x * 128;
    float bb = gnb[f];
    float s = 0.f, mx = 0.f, mc = 0.f, iv = 0.f;
    int cur = -1;
    for (int t = 0; t < 32; t++) {
        int n = base + t * 4 + lane;
        if (n >= NN) break;
        int g = batch[n];
        if (g != cur) {
            if (cur >= 0) {
                atomicAdd(&g_psum[cur * FD + f], s);
                atomicMax((unsigned int*)&g_pmax[cur * FD + f], __float_as_uint(mx));
            }
            cur = g; s = 0.f; mx = 0.f;
            mc = g_mc[g * FD + f];
            iv = g_inv[g * FD + f];
        }
        float v = (g_out[n * FD + f] - mc) * iv + bb + x[n * FD + f];
        v = fmaxf(v, 0.f);
        out[n * FD + f] = v;
        s += v;
        mx = fmaxf(mx, v);
    }
    if (cur >= 0) {
        atomicAdd(&g_psum[cur * FD + f], s);
        atomicMax((unsigned int*)&g_pmax[cur * FD + f], __float_as_uint(mx));
    }
}

// -------- pooled output: flat[g] = [mean_pool | max_pool] --------
__global__ void k_pool(float* __restrict__ out) {
    int i = blockIdx.x * blockDim.x + threadIdx.x;
    if (i >= NG * FD) return;
    int g = i >> 6, f = i & 63;
    float cnt = fmaxf(g_cnt[g], 1.f);
    out[NN * FD + g * 2 * FD + f]      = g_psum[i] / cnt;
    out[NN * FD + g * 2 * FD + FD + f] = g_pmax[i];
}

extern "C" void kernel_launch(void* const* d_in, const int* in_sizes, int n_in,
                              void* d_out, int out_size) {
    const float* x     = (const float*)d_in[0];
    const int*   ei    = (const int*)  d_in[1];
    const int*   batch = (const int*)  d_in[2];
    const float* ew    = (const float*)d_in[3];
    const float* W     = (const float*)d_in[4];
    const float* b     = (const float*)d_in[5];
    const float* gnw   = (const float*)d_in[6];
    const float* gnb   = (const float*)d_in[7];
    const float* ms    = (const float*)d_in[8];
    const int* src = ei;
    const int* dst = ei + NE;
    float* out = (float*)d_out;

    k_zero<<<(NG * FD + 255) / 256 > (NN + 255) / 256 ? (NG * FD + 255) / 256
                                                      : (NN + 255) / 256, 256>>>();
    k_deg<<<(NE + 255) / 256, 256>>>(dst, ew);
    k_scan<<<1, 1024>>>();
    k_build<<<(NE + 255) / 256, 256>>>(src, dst, ew);
    k_hop1<<<(NN * 16 + 255) / 256, 256>>>(x);
    k_hop2<<<(NN * 16 + 255) / 256, 256>>>();
    k_hop3<<<(NN * 16 + 255) / 256, 256>>>();
    k_gemm<<<(NN + 63) / 64, 256>>>(x, W, b);
    k_stats<<<(NN + 127) / 128, 256>>>(batch);
    k_meanvar<<<(NG * FD + 255) / 256, 256>>>(gnw, ms);
    k_final<<<(NN + 127) / 128, 256>>>(x, batch, gnb, out);
    k_pool<<<(NG * FD + 255) / 256, 256>>>(out);
}

// round 6
// speedup vs baseline: 1.0534x; 1.0534x over previous
#include <cuda_runtime.h>
#include <cuda_fp16.h>

#define NN 100000
#define NE 1600000
#define FD 64
#define NG 64
#define EPSV 1e-5f

// -------- scratch (device globals: no allocation allowed) --------
__device__ float g_deg[NN];                    // weighted in-degree
__device__ int   g_cntI[NN];                   // integer in-degree
__device__ int   g_ptr[NN + 1];                // CSR row pointers (by dst)
__device__ int   g_fill[NN];                   // running fill cursors
__device__ __align__(16) int2 g_edge[NE];      // CSR: {src, float_bits(norm)} per slot
__device__ __half g_x16[NN * FD];              // fp16 shadow of x (gathered by hop1)
__device__ __half g_h1h[NN * FD];              // fp16 shadow of h1 (gathered by hop2)
__device__ __half g_h2h[NN * FD];              // fp16 shadow of h2 (gathered by hop3)
__device__ float g_h1[NN * FD];                // fp32 for GEMM
__device__ float g_h2[NN * FD];
__device__ float g_h3[NN * FD];
__device__ float g_out[NN * FD];
__device__ float g_sum[NG * FD];
__device__ float g_sq[NG * FD];
__device__ float g_cnt[NG];
__device__ float g_psum[NG * FD];
__device__ float g_pmax[NG * FD];   // values >= 0 so uint order == float order
__device__ float g_mc[NG * FD];     // mean * mean_scale
__device__ float g_inv[NG * FD];    // gn_weight * rsqrt(var + eps)

// -------- zero scratch --------
__global__ void k_zero() {
    int i = blockIdx.x * blockDim.x + threadIdx.x;
    if (i < NN) { g_deg[i] = 0.f; g_cntI[i] = 0; }
    if (i < NG * FD) { g_sum[i] = 0.f; g_sq[i] = 0.f; g_psum[i] = 0.f; g_pmax[i] = 0.f; }
    if (i < NG) g_cnt[i] = 0.f;
}

// -------- x -> fp16 shadow --------
__global__ void k_x16(const float* __restrict__ x) {
    int i = blockIdx.x * blockDim.x + threadIdx.x;   // one per 4 floats
    if (i >= NN * FD / 4) return;
    float4 v = __ldg((const float4*)x + i);
    __half2 a = __floats2half2_rn(v.x, v.y);
    __half2 b = __floats2half2_rn(v.z, v.w);
    ((__half2*)g_x16)[i * 2]     = a;
    ((__half2*)g_x16)[i * 2 + 1] = b;
}

// -------- degree: weighted + integer count --------
__global__ void k_deg(const int* __restrict__ dst, const float* __restrict__ ew) {
    int e = blockIdx.x * blockDim.x + threadIdx.x;
    if (e >= NE) return;
    int d = dst[e];
    atomicAdd(&g_deg[d], ew[e]);
    atomicAdd(&g_cntI[d], 1);
}

// -------- exclusive prefix scan over g_cntI -> g_ptr / g_fill (single block) --------
__global__ void k_scan() {
    __shared__ int sp[1024];
    const int T = 1024;
    const int CH = (NN + T - 1) / T;       // 98
    int t = threadIdx.x;
    int lo = t * CH, hi = min(lo + CH, NN);
    int s = 0;
    for (int i = lo; i < hi; i++) s += g_cntI[i];
    sp[t] = s;
    __syncthreads();
    for (int off = 1; off < T; off <<= 1) {
        int v = (t >= off) ? sp[t - off] : 0;
        __syncthreads();
        sp[t] += v;
        __syncthreads();
    }
    int run = sp[t] - s;                   // exclusive offset for this chunk
    for (int i = lo; i < hi; i++) {
        g_ptr[i] = run;
        g_fill[i] = run;
        run += g_cntI[i];
    }
    if (t == T - 1) g_ptr[NN] = NE;
}

// -------- build CSR slots (folds norm computation, packed int2 store) --------
__global__ void k_build(const int* __restrict__ src, const int* __restrict__ dst,
                        const float* __restrict__ ew) {
    int e = blockIdx.x * blockDim.x + threadIdx.x;
    if (e >= NE) return;
    int s = src[e], d = dst[e];
    float ds = g_deg[s], dd = g_deg[d];
    float a = (ds > 0.f) ? rsqrtf(ds) : 0.f;
    float c = (dd > 0.f) ? rsqrtf(dd) : 0.f;
    float nrm = a * ew[e] * c;
    int pos = atomicAdd(&g_fill[d], 1);
    g_edge[pos] = make_int2(s, __float_as_int(nrm));
}

// -------- gather hop (fp16 in, fp32 accumulate) --------
// 8 threads per node; thread owns 8 consecutive features (one LDG.128 of halves).
// Metadata for 2 edges fetched in a single int4 load.
__device__ __forceinline__ void hop_accum(float* acc, const __half* __restrict__ hin,
                                          int s, float w, int c) {
    float4 raw = __ldg((const float4*)(hin + (size_t)s * FD + c));
    const __half2* h2 = (const __half2*)&raw;
    #pragma unroll
    for (int q = 0; q < 4; q++) {
        float2 f = __half22float2(h2[q]);
        acc[q * 2]     += w * f.x;
        acc[q * 2 + 1] += w * f.y;
    }
}

template <bool WRITE_HALF>
__device__ __forceinline__ void hop_body(const __half* __restrict__ hin,
                                         float* __restrict__ hout,
                                         __half* __restrict__ houth) {
    unsigned tid = blockIdx.x * blockDim.x + threadIdx.x;
    unsigned node = tid >> 3;
    if (node >= NN) return;
    int c = (tid & 7) * 8;
    int beg = g_ptr[node];
    int end = g_ptr[node + 1];
    float acc[8] = {0.f, 0.f, 0.f, 0.f, 0.f, 0.f, 0.f, 0.f};
    int i = beg;
    if (i < end && (i & 1)) {                       // align to even slot
        int2 m = __ldg(&g_edge[i]);
        hop_accum(acc, hin, m.x, __int_as_float(m.y), c);
        i++;
    }
    for (; i + 2 <= end; i += 2) {
        int4 m = __ldg((const int4*)&g_edge[i]);    // two edges
        hop_accum(acc, hin, m.x, __int_as_float(m.y), c);
        hop_accum(acc, hin, m.z, __int_as_float(m.w), c);
    }
    if (i < end) {
        int2 m = __ldg(&g_edge[i]);
        hop_accum(acc, hin, m.x, __int_as_float(m.y), c);
    }
    float* po = hout + (size_t)node * FD + c;
    *(float4*)(po)     = make_float4(acc[0], acc[1], acc[2], acc[3]);
    *(float4*)(po + 4) = make_float4(acc[4], acc[5], acc[6], acc[7]);
    if (WRITE_HALF) {
        __half2 o[4];
        #pragma unroll
        for (int q = 0; q < 4; q++) o[q] = __floats2half2_rn(acc[q * 2], acc[q * 2 + 1]);
        *(float4*)(houth + (size_t)node * FD + c) = *(float4*)o;   // 8 halves = 16B
    }
}

__global__ void k_hop1() { hop_body<true >(g_x16, g_h1, g_h1h); }
__global__ void k_hop2() { hop_body<true >(g_h1h, g_h2, g_h2h); }
__global__ void k_hop3() { hop_body<false>(g_h2h, g_h3, nullptr); }

// -------- out = x@W0 + h1@W1 + h2@W2 + h3@W3 + b --------
__global__ void k_gemm(const float* __restrict__ x, const float* __restrict__ W,
                       const float* __restrict__ b) {
    __shared__ float Ws[FD * FD];
    int grp = threadIdx.x >> 4;
    int j   = threadIdx.x & 15;
    int node0 = blockIdx.x * 64 + grp * 4;

    float4 acc0 = {0,0,0,0}, acc1 = {0,0,0,0}, acc2 = {0,0,0,0}, acc3 = {0,0,0,0};

    int n0 = min(node0 + 0, NN - 1);
    int n1 = min(node0 + 1, NN - 1);
    int n2 = min(node0 + 2, NN - 1);
    int n3 = min(node0 + 3, NN - 1);

    const float* hs[4] = { x, g_h1, g_h2, g_h3 };

    for (int k = 0; k < 4; k++) {
        for (int t = threadIdx.x; t < FD * FD; t += 256) Ws[t] = W[k * FD * FD + t];
        __syncthreads();
        const float* __restrict__ h = hs[k];
        #pragma unroll
        for (int i = 0; i < FD; i += 4) {
            float4 w0 = *(const float4*)&Ws[(i + 0) * FD + j * 4];
            float4 w1 = *(const float4*)&Ws[(i + 1) * FD + j * 4];
            float4 w2 = *(const float4*)&Ws[(i + 2) * FD + j * 4];
            float4 w3 = *(const float4*)&Ws[(i + 3) * FD + j * 4];
            float4 h0 = *(const float4*)&h[n0 * FD + i];
            float4 h1 = *(const float4*)&h[n1 * FD + i];
            float4 h2 = *(const float4*)&h[n2 * FD + i];
            float4 h3 = *(const float4*)&h[n3 * FD + i];
            acc0.x += h0.x*w0.x + h0.y*w1.x + h0.z*w2.x + h0.w*w3.x;
            acc0.y += h0.x*w0.y + h0.y*w1.y + h0.z*w2.y + h0.w*w3.y;
            acc0.z += h0.x*w0.z + h0.y*w1.z + h0.z*w2.z + h0.w*w3.z;
            acc0.w += h0.x*w0.w + h0.y*w1.w + h0.z*w2.w + h0.w*w3.w;
            acc1.x += h1.x*w0.x + h1.y*w1.x + h1.z*w2.x + h1.w*w3.x;
            acc1.y += h1.x*w0.y + h1.y*w1.y + h1.z*w2.y + h1.w*w3.y;
            acc1.z += h1.x*w0.z + h1.y*w1.z + h1.z*w2.z + h1.w*w3.z;
            acc1.w += h1.x*w0.w + h1.y*w1.w + h1.z*w2.w + h1.w*w3.w;
            acc2.x += h2.x*w0.x + h2.y*w1.x + h2.z*w2.x + h2.w*w3.x;
            acc2.y += h2.x*w0.y + h2.y*w1.y + h2.z*w2.y + h2.w*w3.y;
            acc2.z += h2.x*w0.z + h2.y*w1.z + h2.z*w2.z + h2.w*w3.z;
            acc2.w += h2.x*w0.w + h2.y*w1.w + h2.z*w2.w + h2.w*w3.w;
            acc3.x += h3.x*w0.x + h3.y*w1.x + h3.z*w2.x + h3.w*w3.x;
            acc3.y += h3.x*w0.y + h3.y*w1.y + h3.z*w2.y + h3.w*w3.y;
            acc3.z += h3.x*w0.z + h3.y*w1.z + h3.z*w2.z + h3.w*w3.z;
            acc3.w += h3.x*w0.w + h3.y*w1.w + h3.z*w2.w + h3.w*w3.w;
        }
        __syncthreads();
    }

    float4 bv = *(const float4*)&b[j * 4];
    acc0.x += bv.x; acc0.y += bv.y; acc0.z += bv.z; acc0.w += bv.w;
    acc1.x += bv.x; acc1.y += bv.y; acc1.z += bv.z; acc1.w += bv.w;
    acc2.x += bv.x; acc2.y += bv.y; acc2.z += bv.z; acc2.w += bv.w;
    acc3.x += bv.x; acc3.y += bv.y; acc3.z += bv.z; acc3.w += bv.w;

    if (node0 + 0 < NN) *(float4*)&g_out[(node0 + 0) * FD + j * 4] = acc0;
    if (node0 + 1 < NN) *(float4*)&g_out[(node0 + 1) * FD + j * 4] = acc1;
    if (node0 + 2 < NN) *(float4*)&g_out[(node0 + 2) * FD + j * 4] = acc2;
    if (node0 + 3 < NN) *(float4*)&g_out[(node0 + 3) * FD + j * 4] = acc3;
}

// -------- per-graph sum / sumsq / count over g_out (batch sorted) --------
__global__ void k_stats(const int* __restrict__ batch) {
    int f    = threadIdx.x & 63;
    int lane = threadIdx.x >> 6;   // 0..3
    int base = blockIdx.x * 128;
    float s = 0.f, q = 0.f, c = 0.f;
    int cur = -1;
    for (int t = 0; t < 32; t++) {
        int n = base + t * 4 + lane;
        if (n >= NN) break;
        int g = batch[n];
        if (g != cur) {
            if (cur >= 0) {
                atomicAdd(&g_sum[cur * FD + f], s);
                atomicAdd(&g_sq[cur * FD + f], q);
                if (f == 0) atomicAdd(&g_cnt[cur], c);
            }
            cur = g; s = 0.f; q = 0.f; c = 0.f;
        }
        float v = g_out[n * FD + f];
        s += v; q += v * v; c += 1.f;
    }
    if (cur >= 0) {
        atomicAdd(&g_sum[cur * FD + f], s);
        atomicAdd(&g_sq[cur * FD + f], q);
        if (f == 0) atomicAdd(&g_cnt[cur], c);
    }
}

// -------- mean/var -> premultiplied center & inv-std --------
__global__ void k_meanvar(const float* __restrict__ gnw, const float* __restrict__ ms) {
    int i = blockIdx.x * blockDim.x + threadIdx.x;
    if (i >= NG * FD) return;
    int g = i >> 6, f = i & 63;
    float cnt  = fmaxf(g_cnt[g], 1.f);
    float mean = g_sum[i] / cnt;
    float m    = ms[f];
    float var = g_sq[i] / cnt - 2.f * m * mean * mean + m * m * mean * mean;
    g_mc[i]  = mean * m;
    g_inv[i] = gnw[f] * rsqrtf(var + EPSV);
}

// -------- final: h_emb = relu(gn(out) + x), accumulate pool sum/max --------
__global__ void k_final(const float* __restrict__ x, const int* __restrict__ batch,
                        const float* __restrict__ gnb, float* __restrict__ out) {
    int f    = threadIdx.x & 63;
    int lane = threadIdx.x >> 6;
    int base = blockIdx.x * 128;
    float bb = gnb[f];
    float s = 0.f, mx = 0.f, mc = 0.f, iv = 0.f;
    int cur = -1;
    for (int t = 0; t < 32; t++) {
        int n = base + t * 4 + lane;
        if (n >= NN) break;
        int g = batch[n];
        if (g != cur) {
            if (cur >= 0) {
                atomicAdd(&g_psum[cur * FD + f], s);
                atomicMax((unsigned int*)&g_pmax[cur * FD + f], __float_as_uint(mx));
            }
            cur = g; s = 0.f; mx = 0.f;
            mc = g_mc[g * FD + f];
            iv = g_inv[g * FD + f];
        }
        float v = (g_out[n * FD + f] - mc) * iv + bb + x[n * FD + f];
        v = fmaxf(v, 0.f);
        out[n * FD + f] = v;
        s += v;
        mx = fmaxf(mx, v);
    }
    if (cur >= 0) {
        atomicAdd(&g_psum[cur * FD + f], s);
        atomicMax((unsigned int*)&g_pmax[cur * FD + f], __float_as_uint(mx));
    }
}

// -------- pooled output: flat[g] = [mean_pool | max_pool] --------
__global__ void k_pool(float* __restrict__ out) {
    int i = blockIdx.x * blockDim.x + threadIdx.x;
    if (i >= NG * FD) return;
    int g = i >> 6, f = i & 63;
    float cnt = fmaxf(g_cnt[g], 1.f);
    out[NN * FD + g * 2 * FD + f]      = g_psum[i] / cnt;
    out[NN * FD + g * 2 * FD + FD + f] = g_pmax[i];
}

extern "C" void kernel_launch(void* const* d_in, const int* in_sizes, int n_in,
                              void* d_out, int out_size) {
    const float* x     = (const float*)d_in[0];
    const int*   ei    = (const int*)  d_in[1];
    const int*   batch = (const int*)  d_in[2];
    const float* ew    = (const float*)d_in[3];
    const float* W     = (const float*)d_in[4];
    const float* b     = (const float*)d_in[5];
    const float* gnw   = (const float*)d_in[6];
    const float* gnb   = (const float*)d_in[7];
    const float* ms    = (const float*)d_in[8];
    const int* src = ei;
    const int* dst = ei + NE;
    float* out = (float*)d_out;

    int zgrid = (NN + 255) / 256;
    k_zero<<<zgrid, 256>>>();
    k_x16<<<(NN * FD / 4 + 255) / 256, 256>>>(x);
    k_deg<<<(NE + 255) / 256, 256>>>(dst, ew);
    k_scan<<<1, 1024>>>();
    k_build<<<(NE + 255) / 256, 256>>>(src, dst, ew);
    k_hop1<<<(NN * 8 + 255) / 256, 256>>>();
    k_hop2<<<(NN * 8 + 255) / 256, 256>>>();
    k_hop3<<<(NN * 8 + 255) / 256, 256>>>();
    k_gemm<<<(NN + 63) / 64, 256>>>(x, W, b);
    k_stats<<<(NN + 127) / 128, 256>>>(batch);
    k_meanvar<<<(NG * FD + 255) / 256, 256>>>(gnw, ms);
    k_final<<<(NN + 127) / 128, 256>>>(x, batch, gnb, out);
    k_pool<<<(NG * FD + 255) / 256, 256>>>(out);
}

// round 10
// speedup vs baseline: 1.5463x; 1.4680x over previous
#include <cuda_runtime.h>
#include <cuda_fp16.h>

#define NN 100000
#define NE 1600000
#define FD 64
#define NG 64
#define EPSV 1e-5f
#define NB ((NN + 255) / 256)   // 391 scan blocks

// -------- scratch (device globals: no allocation allowed) --------
__device__ float g_deg[NN];                    // weighted in-degree
__device__ int   g_cntI[NN];                   // integer in-degree
__device__ int   g_bsum[NB];                   // per-block sums for scan
__device__ int   g_ptr[NN + 1];                // CSR row pointers (by dst)
__device__ int   g_fill[NN];                   // running fill cursors
__device__ __align__(16) int2 g_edge[NE];      // CSR: {src, float_bits(norm)} per slot
__device__ __half g_x16[NN * FD];              // fp16 shadow of x (gathered by hop1)
__device__ __half g_h1h[NN * FD];              // fp16 shadow of h1 (gathered by hop2)
__device__ __half g_h2h[NN * FD];              // fp16 shadow of h2 (gathered by hop3)
__device__ float g_h1[NN * FD];                // fp32 for GEMM
__device__ float g_h2[NN * FD];
__device__ float g_h3[NN * FD];
__device__ float g_out[NN * FD];
__device__ float g_sum[NG * FD];
__device__ float g_sq[NG * FD];
__device__ float g_cnt[NG];
__device__ float g_psum[NG * FD];
__device__ float g_pmax[NG * FD];   // values >= 0 so uint order == float order
__device__ float g_mc[NG * FD];     // mean * mean_scale
__device__ float g_inv[NG * FD];    // gn_weight * rsqrt(var + eps)

// -------- zero scratch --------
__global__ void k_zero() {
    int i = blockIdx.x * blockDim.x + threadIdx.x;
    if (i < NN) { g_deg[i] = 0.f; g_cntI[i] = 0; }
    if (i < NG * FD) { g_sum[i] = 0.f; g_sq[i] = 0.f; g_psum[i] = 0.f; g_pmax[i] = 0.f; }
    if (i < NG) g_cnt[i] = 0.f;
}

// -------- x -> fp16 shadow --------
__global__ void k_x16(const float* __restrict__ x) {
    int i = blockIdx.x * blockDim.x + threadIdx.x;   // one per 4 floats
    if (i >= NN * FD / 4) return;
    float4 v = __ldg((const float4*)x + i);
    __half2 a = __floats2half2_rn(v.x, v.y);
    __half2 b = __floats2half2_rn(v.z, v.w);
    ((__half2*)g_x16)[i * 2]     = a;
    ((__half2*)g_x16)[i * 2 + 1] = b;
}

// -------- degree: weighted + integer count --------
__global__ void k_deg(const int* __restrict__ dst, const float* __restrict__ ew) {
    int e = blockIdx.x * blockDim.x + threadIdx.x;
    if (e >= NE) return;
    int d = dst[e];
    atomicAdd(&g_deg[d], ew[e]);
    atomicAdd(&g_cntI[d], 1);
}

// -------- multi-block exclusive scan of g_cntI -> g_ptr / g_fill --------
// phase 1: per-block reduce
__global__ void k_scan1() {
    int i = blockIdx.x * 256 + threadIdx.x;
    int v = (i < NN) ? g_cntI[i] : 0;
    __shared__ int sw[8];
    #pragma unroll
    for (int o = 16; o; o >>= 1) v += __shfl_down_sync(0xffffffffu, v, o);
    if ((threadIdx.x & 31) == 0) sw[threadIdx.x >> 5] = v;
    __syncthreads();
    if (threadIdx.x < 8) {
        int t = sw[threadIdx.x];
        #pragma unroll
        for (int o = 4; o; o >>= 1) t += __shfl_down_sync(0xffu, t, o);
        if (threadIdx.x == 0) g_bsum[blockIdx.x] = t;
    }
}
// phase 2: single small block scans the block sums (NB <= 512)
__global__ void k_scan2() {
    __shared__ int sp[512];
    int t = threadIdx.x;
    int v = (t < NB) ? g_bsum[t] : 0;
    sp[t] = v;
    __syncthreads();
    for (int off = 1; off < 512; off <<= 1) {
        int u = (t >= off) ? sp[t - off] : 0;
        __syncthreads();
        sp[t] += u;
        __syncthreads();
    }
    if (t < NB) g_bsum[t] = sp[t] - v;   // exclusive block offsets
    if (t == 0) g_ptr[NN] = NE;
}
// phase 3: block-local exclusive scan + block offset
__global__ void k_scan3() {
    __shared__ int sp[256];
    int i = blockIdx.x * 256 + threadIdx.x;
    int v = (i < NN) ? g_cntI[i] : 0;
    sp[threadIdx.x] = v;
    __syncthreads();
    for (int off = 1; off < 256; off <<= 1) {
        int u = (threadIdx.x >= off) ? sp[threadIdx.x - off] : 0;
        __syncthreads();
        sp[threadIdx.x] += u;
        __syncthreads();
    }
    if (i < NN) {
        int p = g_bsum[blockIdx.x] + sp[threadIdx.x] - v;  // exclusive
        g_ptr[i] = p;
        g_fill[i] = p;
    }
}

// -------- build CSR slots (folds norm computation, packed int2 store) --------
__global__ void k_build(const int* __restrict__ src, const int* __restrict__ dst,
                        const float* __restrict__ ew) {
    int e = blockIdx.x * blockDim.x + threadIdx.x;
    if (e >= NE) return;
    int s = src[e], d = dst[e];
    float ds = g_deg[s], dd = g_deg[d];
    float a = (ds > 0.f) ? rsqrtf(ds) : 0.f;
    float c = (dd > 0.f) ? rsqrtf(dd) : 0.f;
    float nrm = a * ew[e] * c;
    int pos = atomicAdd(&g_fill[d], 1);
    g_edge[pos] = make_int2(s, __float_as_int(nrm));
}

// -------- gather hop (fp16 in, fp32 accumulate) --------
__device__ __forceinline__ void hop_accum(float* acc, const __half* __restrict__ hin,
                                          int s, float w, int c) {
    float4 raw = __ldg((const float4*)(hin + (size_t)s * FD + c));
    const __half2* h2 = (const __half2*)&raw;
    #pragma unroll
    for (int q = 0; q < 4; q++) {
        float2 f = __half22float2(h2[q]);
        acc[q * 2]     += w * f.x;
        acc[q * 2 + 1] += w * f.y;
    }
}

template <bool WRITE_HALF>
__device__ __forceinline__ void hop_body(const __half* __restrict__ hin,
                                         float* __restrict__ hout,
                                         __half* __restrict__ houth) {
    unsigned tid = blockIdx.x * blockDim.x + threadIdx.x;
    unsigned node = tid >> 3;
    if (node >= NN) return;
    int c = (tid & 7) * 8;
    int beg = g_ptr[node];
    int end = g_ptr[node + 1];
    float acc[8] = {0.f, 0.f, 0.f, 0.f, 0.f, 0.f, 0.f, 0.f};
    int i = beg;
    if (i < end && (i & 1)) {
        int2 m = __ldg(&g_edge[i]);
        hop_accum(acc, hin, m.x, __int_as_float(m.y), c);
        i++;
    }
    for (; i + 2 <= end; i += 2) {
        int4 m = __ldg((const int4*)&g_edge[i]);
        hop_accum(acc, hin, m.x, __int_as_float(m.y), c);
        hop_accum(acc, hin, m.z, __int_as_float(m.w), c);
    }
    if (i < end) {
        int2 m = __ldg(&g_edge[i]);
        hop_accum(acc, hin, m.x, __int_as_float(m.y), c);
    }
    float* po = hout + (size_t)node * FD + c;
    *(float4*)(po)     = make_float4(acc[0], acc[1], acc[2], acc[3]);
    *(float4*)(po + 4) = make_float4(acc[4], acc[5], acc[6], acc[7]);
    if (WRITE_HALF) {
        __half2 o[4];
        #pragma unroll
        for (int q = 0; q < 4; q++) o[q] = __floats2half2_rn(acc[q * 2], acc[q * 2 + 1]);
        *(float4*)(houth + (size_t)node * FD + c) = *(float4*)o;
    }
}

__global__ void k_hop1() { hop_body<true >(g_x16, g_h1, g_h1h); }
__global__ void k_hop2() { hop_body<true >(g_h1h, g_h2, g_h2h); }
__global__ void k_hop3() { hop_body<false>(g_h2h, g_h3, nullptr); }

// -------- out = x@W0 + h1@W1 + h2@W2 + h3@W3 + b --------
__global__ void k_gemm(const float* __restrict__ x, const float* __restrict__ W,
                       const float* __restrict__ b) {
    __shared__ float Ws[FD * FD];
    int grp = threadIdx.x >> 4;
    int j   = threadIdx.x & 15;
    int node0 = blockIdx.x * 64 + grp * 4;

    float4 acc0 = {0,0,0,0}, acc1 = {0,0,0,0}, acc2 = {0,0,0,0}, acc3 = {0,0,0,0};

    int n0 = min(node0 + 0, NN - 1);
    int n1 = min(node0 + 1, NN - 1);
    int n2 = min(node0 + 2, NN - 1);
    int n3 = min(node0 + 3, NN - 1);

    const float* hs[4] = { x, g_h1, g_h2, g_h3 };

    for (int k = 0; k < 4; k++) {
        for (int t = threadIdx.x; t < FD * FD; t += 256) Ws[t] = W[k * FD * FD + t];
        __syncthreads();
        const float* __restrict__ h = hs[k];
        #pragma unroll
        for (int i = 0; i < FD; i += 4) {
            float4 w0 = *(const float4*)&Ws[(i + 0) * FD + j * 4];
            float4 w1 = *(const float4*)&Ws[(i + 1) * FD + j * 4];
            float4 w2 = *(const float4*)&Ws[(i + 2) * FD + j * 4];
            float4 w3 = *(const float4*)&Ws[(i + 3) * FD + j * 4];
            float4 h0 = *(const float4*)&h[n0 * FD + i];
            float4 h1 = *(const float4*)&h[n1 * FD + i];
            float4 h2 = *(const float4*)&h[n2 * FD + i];
            float4 h3 = *(const float4*)&h[n3 * FD + i];
            acc0.x += h0.x*w0.x + h0.y*w1.x + h0.z*w2.x + h0.w*w3.x;
            acc0.y += h0.x*w0.y + h0.y*w1.y + h0.z*w2.y + h0.w*w3.y;
            acc0.z += h0.x*w0.z + h0.y*w1.z + h0.z*w2.z + h0.w*w3.z;
            acc0.w += h0.x*w0.w + h0.y*w1.w + h0.z*w2.w + h0.w*w3.w;
            acc1.x += h1.x*w0.x + h1.y*w1.x + h1.z*w2.x + h1.w*w3.x;
            acc1.y += h1.x*w0.y + h1.y*w1.y + h1.z*w2.y + h1.w*w3.y;
            acc1.z += h1.x*w0.z + h1.y*w1.z + h1.z*w2.z + h1.w*w3.z;
            acc1.w += h1.x*w0.w + h1.y*w1.w + h1.z*w2.w + h1.w*w3.w;
            acc2.x += h2.x*w0.x + h2.y*w1.x + h2.z*w2.x + h2.w*w3.x;
            acc2.y += h2.x*w0.y + h2.y*w1.y + h2.z*w2.y + h2.w*w3.y;
            acc2.z += h2.x*w0.z + h2.y*w1.z + h2.z*w2.z + h2.w*w3.z;
            acc2.w += h2.x*w0.w + h2.y*w1.w + h2.z*w2.w + h2.w*w3.w;
            acc3.x += h3.x*w0.x + h3.y*w1.x + h3.z*w2.x + h3.w*w3.x;
            acc3.y += h3.x*w0.y + h3.y*w1.y + h3.z*w2.y + h3.w*w3.y;
            acc3.z += h3.x*w0.z + h3.y*w1.z + h3.z*w2.z + h3.w*w3.z;
            acc3.w += h3.x*w0.w + h3.y*w1.w + h3.z*w2.w + h3.w*w3.w;
        }
        __syncthreads();
    }

    float4 bv = *(const float4*)&b[j * 4];
    acc0.x += bv.x; acc0.y += bv.y; acc0.z += bv.z; acc0.w += bv.w;
    acc1.x += bv.x; acc1.y += bv.y; acc1.z += bv.z; acc1.w += bv.w;
    acc2.x += bv.x; acc2.y += bv.y; acc2.z += bv.z; acc2.w += bv.w;
    acc3.x += bv.x; acc3.y += bv.y; acc3.z += bv.z; acc3.w += bv.w;

    if (node0 + 0 < NN) *(float4*)&g_out[(node0 + 0) * FD + j * 4] = acc0;
    if (node0 + 1 < NN) *(float4*)&g_out[(node0 + 1) * FD + j * 4] = acc1;
    if (node0 + 2 < NN) *(float4*)&g_out[(node0 + 2) * FD + j * 4] = acc2;
    if (node0 + 3 < NN) *(float4*)&g_out[(node0 + 3) * FD + j * 4] = acc3;
}

// -------- per-graph sum / sumsq / count over g_out (batch sorted) --------
__global__ void k_stats(const int* __restrict__ batch) {
    int f    = threadIdx.x & 63;
    int lane = threadIdx.x >> 6;   // 0..3
    int base = blockIdx.x * 128;
    float s = 0.f, q = 0.f, c = 0.f;
    int cur = -1;
    for (int t = 0; t < 32; t++) {
        int n = base + t * 4 + lane;
        if (n >= NN) break;
        int g = batch[n];
        if (g != cur) {
            if (cur >= 0) {
                atomicAdd(&g_sum[cur * FD + f], s);
                atomicAdd(&g_sq[cur * FD + f], q);
                if (f == 0) atomicAdd(&g_cnt[cur], c);
            }
            cur = g; s = 0.f; q = 0.f; c = 0.f;
        }
        float v = g_out[n * FD + f];
        s += v; q += v * v; c += 1.f;
    }
    if (cur >= 0) {
        atomicAdd(&g_sum[cur * FD + f], s);
        atomicAdd(&g_sq[cur * FD + f], q);
        if (f == 0) atomicAdd(&g_cnt[cur], c);
    }
}

// -------- mean/var -> premultiplied center & inv-std --------
__global__ void k_meanvar(const float* __restrict__ gnw, const float* __restrict__ ms) {
    int i = blockIdx.x * blockDim.x + threadIdx.x;
    if (i >= NG * FD) return;
    int g = i >> 6, f = i & 63;
    float cnt  = fmaxf(g_cnt[g], 1.f);
    float mean = g_sum[i] / cnt;
    float m    = ms[f];
    float var = g_sq[i] / cnt - 2.f * m * mean * mean + m * m * mean * mean;
    g_mc[i]  = mean * m;
    g_inv[i] = gnw[f] * rsqrtf(var + EPSV);
}

// -------- final: h_emb = relu(gn(out) + x), accumulate pool sum/max --------
__global__ void k_final(const float* __restrict__ x, const int* __restrict__ batch,
                        const float* __restrict__ gnb, float* __restrict__ out) {
    int f    = threadIdx.x & 63;
    int lane = threadIdx.x >> 6;
    int base = blockIdx.x * 128;
    float bb = gnb[f];
    float s = 0.f, mx = 0.f, mc = 0.f, iv = 0.f;
    int cur = -1;
    for (int t = 0; t < 32; t++) {
        int n = base + t * 4 + lane;
        if (n >= NN) break;
        int g = batch[n];
        if (g != cur) {
            if (cur >= 0) {
                atomicAdd(&g_psum[cur * FD + f], s);
                atomicMax((unsigned int*)&g_pmax[cur * FD + f], __float_as_uint(mx));
            }
            cur = g; s = 0.f; mx = 0.f;
            mc = g_mc[g * FD + f];
            iv = g_inv[g * FD + f];
        }
        float v = (g_out[n * FD + f] - mc) * iv + bb + x[n * FD + f];
        v = fmaxf(v, 0.f);
        out[n * FD + f] = v;
        s += v;
        mx = fmaxf(mx, v);
    }
    if (cur >= 0) {
        atomicAdd(&g_psum[cur * FD + f], s);
        atomicMax((unsigned int*)&g_pmax[cur * FD + f], __float_as_uint(mx));
    }
}

// -------- pooled output: flat[g] = [mean_pool | max_pool] --------
__global__ void k_pool(float* __restrict__ out) {
    int i = blockIdx.x * blockDim.x + threadIdx.x;
    if (i >= NG * FD) return;
    int g = i >> 6, f = i & 63;
    float cnt = fmaxf(g_cnt[g], 1.f);
    out[NN * FD + g * 2 * FD + f]      = g_psum[i] / cnt;
    out[NN * FD + g * 2 * FD + FD + f] = g_pmax[i];
}

extern "C" void kernel_launch(void* const* d_in, const int* in_sizes, int n_in,
                              void* d_out, int out_size) {
    const float* x     = (const float*)d_in[0];
    const int*   ei    = (const int*)  d_in[1];
    const int*   batch = (const int*)  d_in[2];
    const float* ew    = (const float*)d_in[3];
    const float* W     = (const float*)d_in[4];
    const float* b     = (const float*)d_in[5];
    const float* gnw   = (const float*)d_in[6];
    const float* gnb   = (const float*)d_in[7];
    const float* ms    = (const float*)d_in[8];
    const int* src = ei;
    const int* dst = ei + NE;
    float* out = (float*)d_out;

    k_zero<<<(NN + 255) / 256, 256>>>();
    k_x16<<<(NN * FD / 4 + 255) / 256, 256>>>(x);
    k_deg<<<(NE + 255) / 256, 256>>>(dst, ew);
    k_scan1<<<NB, 256>>>();
    k_scan2<<<1, 512>>>();
    k_scan3<<<NB, 256>>>();
    k_build<<<(NE + 255) / 256, 256>>>(src, dst, ew);
    k_hop1<<<(NN * 8 + 255) / 256, 256>>>();
    k_hop2<<<(NN * 8 + 255) / 256, 256>>>();
    k_hop3<<<(NN * 8 + 255) / 256, 256>>>();
    k_gemm<<<(NN + 63) / 64, 256>>>(x, W, b);
    k_stats<<<(NN + 127) / 128, 256>>>(batch);
    k_meanvar<<<(NG * FD + 255) / 256, 256>>>(gnw, ms);
    k_final<<<(NN + 127) / 128, 256>>>(x, batch, gnb, out);
    k_pool<<<(NG * FD + 255) / 256, 256>>>(out);
}

// round 11
// speedup vs baseline: 1.6001x; 1.0348x over previous
#include <cuda_runtime.h>
#include <cuda_fp16.h>

#define NN 100000
#define NE 1600000
#define FD 64
#define NG 64
#define EPSV 1e-5f
#define NB ((NN + 255) / 256)   // 391 scan blocks

// -------- scratch (device globals: no allocation allowed) --------
__device__ float g_deg[NN];                    // weighted in-degree
__device__ int   g_cntI[NN];                   // integer in-degree
__device__ int   g_bsum[NB];                   // per-block sums for scan
__device__ int   g_ptr[NN + 1];                // CSR row pointers (by dst)
__device__ int   g_fill[NN];                   // running fill cursors
__device__ __align__(16) int2 g_edge[NE];      // CSR: {src, float_bits(ew)} per slot
__device__ __half g_x16[NN * FD];              // fp16: dis[v] * x[v]
__device__ __half g_h1h[NN * FD];              // fp16: dis[v] * h1[v]
__device__ __half g_h2h[NN * FD];              // fp16: dis[v] * h2[v]
__device__ float g_h1[NN * FD];                // fp32 for GEMM
__device__ float g_h2[NN * FD];
__device__ float g_h3[NN * FD];
__device__ float g_out[NN * FD];
__device__ float g_sum[NG * FD];
__device__ float g_sq[NG * FD];
__device__ float g_cnt[NG];
__device__ float g_psum[NG * FD];
__device__ float g_pmax[NG * FD];   // values >= 0 so uint order == float order
__device__ float g_mc[NG * FD];     // mean * mean_scale
__device__ float g_inv[NG * FD];    // gn_weight * rsqrt(var + eps)

// -------- f32x2 helpers (Blackwell packed fp32 SIMD, PTX-only) --------
__device__ __forceinline__ unsigned long long pk2(float v) {
    unsigned long long r;
    asm("mov.b64 %0, {%1, %1};" : "=l"(r) : "f"(v));
    return r;
}
__device__ __forceinline__ unsigned long long fma2(unsigned long long a,
                                                   unsigned long long b,
                                                   unsigned long long c) {
    unsigned long long d;
    asm("fma.rn.f32x2 %0, %1, %2, %3;" : "=l"(d) : "l"(a), "l"(b), "l"(c));
    return d;
}
__device__ __forceinline__ float2 unpk2(unsigned long long v) {
    float lo, hi;
    asm("mov.b64 {%0, %1}, %2;" : "=f"(lo), "=f"(hi) : "l"(v));
    return make_float2(lo, hi);
}

// -------- zero scratch --------
__global__ void k_zero() {
    int i = blockIdx.x * blockDim.x + threadIdx.x;
    if (i < NN) { g_deg[i] = 0.f; g_cntI[i] = 0; }
    if (i < NG * FD) { g_sum[i] = 0.f; g_sq[i] = 0.f; g_psum[i] = 0.f; g_pmax[i] = 0.f; }
    if (i < NG) g_cnt[i] = 0.f;
}

// -------- degree: weighted + integer count --------
__global__ void k_deg(const int* __restrict__ dst, const float* __restrict__ ew) {
    int e = blockIdx.x * blockDim.x + threadIdx.x;
    if (e >= NE) return;
    int d = dst[e];
    atomicAdd(&g_deg[d], ew[e]);
    atomicAdd(&g_cntI[d], 1);
}

// -------- x -> fp16 shadow premultiplied by dis[v] (AFTER k_deg) --------
__global__ void k_x16(const float* __restrict__ x) {
    int i = blockIdx.x * blockDim.x + threadIdx.x;   // one per 4 floats
    if (i >= NN * FD / 4) return;
    int node = i >> 4;                               // FD/4 = 16 chunks per node
    float dg = g_deg[node];
    float dd = (dg > 0.f) ? rsqrtf(dg) : 0.f;
    float4 v = __ldg((const float4*)x + i);
    __half2 a = __floats2half2_rn(v.x * dd, v.y * dd);
    __half2 b = __floats2half2_rn(v.z * dd, v.w * dd);
    ((__half2*)g_x16)[i * 2]     = a;
    ((__half2*)g_x16)[i * 2 + 1] = b;
}

// -------- multi-block exclusive scan of g_cntI -> g_ptr / g_fill --------
__global__ void k_scan1() {
    int i = blockIdx.x * 256 + threadIdx.x;
    int v = (i < NN) ? g_cntI[i] : 0;
    __shared__ int sw[8];
    #pragma unroll
    for (int o = 16; o; o >>= 1) v += __shfl_down_sync(0xffffffffu, v, o);
    if ((threadIdx.x & 31) == 0) sw[threadIdx.x >> 5] = v;
    __syncthreads();
    if (threadIdx.x < 8) {
        int t = sw[threadIdx.x];
        #pragma unroll
        for (int o = 4; o; o >>= 1) t += __shfl_down_sync(0xffu, t, o);
        if (threadIdx.x == 0) g_bsum[blockIdx.x] = t;
    }
}
__global__ void k_scan2() {
    __shared__ int sp[512];
    int t = threadIdx.x;
    int v = (t < NB) ? g_bsum[t] : 0;
    sp[t] = v;
    __syncthreads();
    for (int off = 1; off < 512; off <<= 1) {
        int u = (t >= off) ? sp[t - off] : 0;
        __syncthreads();
        sp[t] += u;
        __syncthreads();
    }
    if (t < NB) g_bsum[t] = sp[t] - v;
    if (t == 0) g_ptr[NN] = NE;
}
__global__ void k_scan3() {
    __shared__ int sp[256];
    int i = blockIdx.x * 256 + threadIdx.x;
    int v = (i < NN) ? g_cntI[i] : 0;
    sp[threadIdx.x] = v;
    __syncthreads();
    for (int off = 1; off < 256; off <<= 1) {
        int u = (threadIdx.x >= off) ? sp[threadIdx.x - off] : 0;
        __syncthreads();
        sp[threadIdx.x] += u;
        __syncthreads();
    }
    if (i < NN) {
        int p = g_bsum[blockIdx.x] + sp[threadIdx.x] - v;
        g_ptr[i] = p;
        g_fill[i] = p;
    }
}

// -------- build CSR slots: just (src, ew) — no deg gathers --------
__global__ void k_build(const int* __restrict__ src, const int* __restrict__ dst,
                        const float* __restrict__ ew) {
    int e = blockIdx.x * blockDim.x + threadIdx.x;
    if (e >= NE) return;
    int s = src[e], d = dst[e];
    float w = ew[e];
    int pos = atomicAdd(&g_fill[d], 1);
    g_edge[pos] = make_int2(s, __float_as_int(w));
}

// -------- gather hop (fp16 in, fp32 accumulate, dis-premultiplied) --------
__device__ __forceinline__ void hop_math(float* acc, float4 raw, float w) {
    const __half2* h2 = (const __half2*)&raw;
    #pragma unroll
    for (int q = 0; q < 4; q++) {
        float2 f = __half22float2(h2[q]);
        acc[q * 2]     += w * f.x;
        acc[q * 2 + 1] += w * f.y;
    }
}

template <bool WRITE_HALF>
__device__ __forceinline__ void hop_body(const __half* __restrict__ hin,
                                         float* __restrict__ hout,
                                         __half* __restrict__ houth) {
    unsigned tid = blockIdx.x * blockDim.x + threadIdx.x;
    unsigned node = tid >> 3;
    if (node >= NN) return;
    int c = (tid & 7) * 8;
    int beg = g_ptr[node];
    int end = g_ptr[node + 1];
    float acc[8] = {0.f, 0.f, 0.f, 0.f, 0.f, 0.f, 0.f, 0.f};
    int i = beg;
    if (i < end && (i & 1)) {                    // align to even slot
        int2 m = __ldg(&g_edge[i]);
        float4 r = __ldg((const float4*)(hin + (size_t)m.x * FD + c));
        hop_math(acc, r, __int_as_float(m.y));
        i++;
    }
    // 4-edge unrolled main loop: batch all loads first for MLP
    for (; i + 4 <= end; i += 4) {
        int4 m0 = __ldg((const int4*)&g_edge[i]);
        int4 m1 = __ldg((const int4*)&g_edge[i + 2]);
        float4 r0 = __ldg((const float4*)(hin + (size_t)m0.x * FD + c));
        float4 r1 = __ldg((const float4*)(hin + (size_t)m0.z * FD + c));
        float4 r2 = __ldg((const float4*)(hin + (size_t)m1.x * FD + c));
        float4 r3 = __ldg((const float4*)(hin + (size_t)m1.z * FD + c));
        hop_math(acc, r0, __int_as_float(m0.y));
        hop_math(acc, r1, __int_as_float(m0.w));
        hop_math(acc, r2, __int_as_float(m1.y));
        hop_math(acc, r3, __int_as_float(m1.w));
    }
    if (i + 2 <= end) {
        int4 m = __ldg((const int4*)&g_edge[i]);
        float4 r0 = __ldg((const float4*)(hin + (size_t)m.x * FD + c));
        float4 r1 = __ldg((const float4*)(hin + (size_t)m.z * FD + c));
        hop_math(acc, r0, __int_as_float(m.y));
        hop_math(acc, r1, __int_as_float(m.w));
        i += 2;
    }
    if (i < end) {
        int2 m = __ldg(&g_edge[i]);
        float4 r = __ldg((const float4*)(hin + (size_t)m.x * FD + c));
        hop_math(acc, r, __int_as_float(m.y));
    }
    float dg = g_deg[node];
    float dd = (dg > 0.f) ? rsqrtf(dg) : 0.f;
    float h0 = dd * acc[0], h1 = dd * acc[1], h2 = dd * acc[2], h3 = dd * acc[3];
    float h4 = dd * acc[4], h5 = dd * acc[5], h6 = dd * acc[6], h7 = dd * acc[7];
    float* po = hout + (size_t)node * FD + c;
    *(float4*)(po)     = make_float4(h0, h1, h2, h3);
    *(float4*)(po + 4) = make_float4(h4, h5, h6, h7);
    if (WRITE_HALF) {
        __half2 o[4];
        o[0] = __floats2half2_rn(dd * h0, dd * h1);
        o[1] = __floats2half2_rn(dd * h2, dd * h3);
        o[2] = __floats2half2_rn(dd * h4, dd * h5);
        o[3] = __floats2half2_rn(dd * h6, dd * h7);
        *(float4*)(houth + (size_t)node * FD + c) = *(float4*)o;
    }
}

__global__ void k_hop1() { hop_body<true >(g_x16, g_h1, g_h1h); }
__global__ void k_hop2() { hop_body<true >(g_h1h, g_h2, g_h2h); }
__global__ void k_hop3() { hop_body<false>(g_h2h, g_h3, nullptr); }

// -------- out = x@W0 + h1@W1 + h2@W2 + h3@W3 + b (f32x2 packed math) --------
__global__ void k_gemm(const float* __restrict__ x, const float* __restrict__ W,
                       const float* __restrict__ b) {
    __shared__ float Ws[FD * FD];
    int grp = threadIdx.x >> 4;
    int j   = threadIdx.x & 15;
    int node0 = blockIdx.x * 64 + grp * 4;

    // acc[m][0] = outs (4j, 4j+1), acc[m][1] = outs (4j+2, 4j+3), node m
    unsigned long long acc[4][2] = {{0ull,0ull},{0ull,0ull},{0ull,0ull},{0ull,0ull}};

    int n0 = min(node0 + 0, NN - 1);
    int n1 = min(node0 + 1, NN - 1);
    int n2 = min(node0 + 2, NN - 1);
    int n3 = min(node0 + 3, NN - 1);

    const float* hs[4] = { x, g_h1, g_h2, g_h3 };

    for (int k = 0; k < 4; k++) {
        for (int t = threadIdx.x; t < FD * FD; t += 256) Ws[t] = W[k * FD * FD + t];
        __syncthreads();
        const float* __restrict__ h = hs[k];
        #pragma unroll
        for (int i = 0; i < FD; i += 4) {
            float4 h0 = *(const float4*)&h[n0 * FD + i];
            float4 h1 = *(const float4*)&h[n1 * FD + i];
            float4 h2 = *(const float4*)&h[n2 * FD + i];
            float4 h3 = *(const float4*)&h[n3 * FD + i];
            #pragma unroll
            for (int r = 0; r < 4; r++) {
                ulonglong2 w = *(const ulonglong2*)&Ws[(i + r) * FD + j * 4];
                unsigned long long a0 = pk2(((const float*)&h0)[r]);
                unsigned long long a1 = pk2(((const float*)&h1)[r]);
                unsigned long long a2 = pk2(((const float*)&h2)[r]);
                unsigned long long a3 = pk2(((const float*)&h3)[r]);
                acc[0][0] = fma2(a0, w.x, acc[0][0]);
                acc[0][1] = fma2(a0, w.y, acc[0][1]);
                acc[1][0] = fma2(a1, w.x, acc[1][0]);
                acc[1][1] = fma2(a1, w.y, acc[1][1]);
                acc[2][0] = fma2(a2, w.x, acc[2][0]);
                acc[2][1] = fma2(a2, w.y, acc[2][1]);
                acc[3][0] = fma2(a3, w.x, acc[3][0]);
                acc[3][1] = fma2(a3, w.y, acc[3][1]);
            }
        }
        __syncthreads();
    }

    float4 bv = *(const float4*)&b[j * 4];
    #pragma unroll
    for (int m = 0; m < 4; m++) {
        if (node0 + m >= NN) break;
        float2 lo = unpk2(acc[m][0]);
        float2 hi = unpk2(acc[m][1]);
        float4 o = make_float4(lo.x + bv.x, lo.y + bv.y, hi.x + bv.z, hi.y + bv.w);
        *(float4*)&g_out[(node0 + m) * FD + j * 4] = o;
    }
}

// -------- per-graph sum / sumsq / count over g_out (batch sorted) --------
__global__ void k_stats(const int* __restrict__ batch) {
    int f    = threadIdx.x & 63;
    int lane = threadIdx.x >> 6;   // 0..3
    int base = blockIdx.x * 128;
    float s = 0.f, q = 0.f, c = 0.f;
    int cur = -1;
    for (int t = 0; t < 32; t++) {
        int n = base + t * 4 + lane;
        if (n >= NN) break;
        int g = batch[n];
        if (g != cur) {
            if (cur >= 0) {
                atomicAdd(&g_sum[cur * FD + f], s);
                atomicAdd(&g_sq[cur * FD + f], q);
                if (f == 0) atomicAdd(&g_cnt[cur], c);
            }
            cur = g; s = 0.f; q = 0.f; c = 0.f;
        }
        float v = g_out[n * FD + f];
        s += v; q += v * v; c += 1.f;
    }
    if (cur >= 0) {
        atomicAdd(&g_sum[cur * FD + f], s);
        atomicAdd(&g_sq[cur * FD + f], q);
        if (f == 0) atomicAdd(&g_cnt[cur], c);
    }
}

// -------- mean/var -> premultiplied center & inv-std --------
__global__ void k_meanvar(const float* __restrict__ gnw, const float* __restrict__ ms) {
    int i = blockIdx.x * blockDim.x + threadIdx.x;
    if (i >= NG * FD) return;
    int g = i >> 6, f = i & 63;
    float cnt  = fmaxf(g_cnt[g], 1.f);
    float mean = g_sum[i] / cnt;
    float m    = ms[f];
    float var = g_sq[i] / cnt - 2.f * m * mean * mean + m * m * mean * mean;
    g_mc[i]  = mean * m;
    g_inv[i] = gnw[f] * rsqrtf(var + EPSV);
}

// -------- final: h_emb = relu(gn(out) + x), accumulate pool sum/max --------
__global__ void k_final(const float* __restrict__ x, const int* __restrict__ batch,
                        const float* __restrict__ gnb, float* __restrict__ out) {
    int f    = threadIdx.x & 63;
    int lane = threadIdx.x >> 6;
    int base = blockIdx.x * 128;
    float bb = gnb[f];
    float s = 0.f, mx = 0.f, mc = 0.f, iv = 0.f;
    int cur = -1;
    for (int t = 0; t < 32; t++) {
        int n = base + t * 4 + lane;
        if (n >= NN) break;
        int g = batch[n];
        if (g != cur) {
            if (cur >= 0) {
                atomicAdd(&g_psum[cur * FD + f], s);
                atomicMax((unsigned int*)&g_pmax[cur * FD + f], __float_as_uint(mx));
            }
            cur = g; s = 0.f; mx = 0.f;
            mc = g_mc[g * FD + f];
            iv = g_inv[g * FD + f];
        }
        float v = (g_out[n * FD + f] - mc) * iv + bb + x[n * FD + f];
        v = fmaxf(v, 0.f);
        out[n * FD + f] = v;
        s += v;
        mx = fmaxf(mx, v);
    }
    if (cur >= 0) {
        atomicAdd(&g_psum[cur * FD + f], s);
        atomicMax((unsigned int*)&g_pmax[cur * FD + f], __float_as_uint(mx));
    }
}

// -------- pooled output: flat[g] = [mean_pool | max_pool] --------
__global__ void k_pool(float* __restrict__ out) {
    int i = blockIdx.x * blockDim.x + threadIdx.x;
    if (i >= NG * FD) return;
    int g = i >> 6, f = i & 63;
    float cnt = fmaxf(g_cnt[g], 1.f);
    out[NN * FD + g * 2 * FD + f]      = g_psum[i] / cnt;
    out[NN * FD + g * 2 * FD + FD + f] = g_pmax[i];
}

extern "C" void kernel_launch(void* const* d_in, const int* in_sizes, int n_in,
                              void* d_out, int out_size) {
    const float* x     = (const float*)d_in[0];
    const int*   ei    = (const int*)  d_in[1];
    const int*   batch = (const int*)  d_in[2];
    const float* ew    = (const float*)d_in[3];
    const float* W     = (const float*)d_in[4];
    const float* b     = (const float*)d_in[5];
    const float* gnw   = (const float*)d_in[6];
    const float* gnb   = (const float*)d_in[7];
    const float* ms    = (const float*)d_in[8];
    const int* src = ei;
    const int* dst = ei + NE;
    float* out = (float*)d_out;

    k_zero<<<(NN + 255) / 256, 256>>>();
    k_deg<<<(NE + 255) / 256, 256>>>(dst, ew);
    k_x16<<<(NN * FD / 4 + 255) / 256, 256>>>(x);   // after k_deg (needs dis)
    k_scan1<<<NB, 256>>>();
    k_scan2<<<1, 512>>>();
    k_scan3<<<NB, 256>>>();
    k_build<<<(NE + 255) / 256, 256>>>(src, dst, ew);
    k_hop1<<<(NN * 8 + 255) / 256, 256>>>();
    k_hop2<<<(NN * 8 + 255) / 256, 256>>>();
    k_hop3<<<(NN * 8 + 255) / 256, 256>>>();
    k_gemm<<<(NN + 63) / 64, 256>>>(x, W, b);
    k_stats<<<(NN + 127) / 128, 256>>>(batch);
    k_meanvar<<<(NG * FD + 255) / 256, 256>>>(gnw, ms);
    k_final<<<(NN + 127) / 128, 256>>>(x, batch, gnb, out);
    k_pool<<<(NG * FD + 255) / 256, 256>>>(out);
}

// round 12
// speedup vs baseline: 2.3278x; 1.4547x over previous
#include <cuda_runtime.h>
#include <cuda_fp16.h>

#define NN 100000
#define NE 1600000
#define FD 64
#define NG 64
#define EPSV 1e-5f
#define NB ((NN + 255) / 256)   // 391 scan blocks

// -------- scratch (device globals: no allocation allowed) --------
__device__ float g_deg[NN];                    // weighted in-degree
__device__ int   g_cntI[NN];                   // integer in-degree
__device__ int   g_bsum[NB];                   // per-block sums for scan
__device__ int   g_ptr[NN + 1];                // CSR row pointers (by dst)
__device__ int   g_fill[NN];                   // running fill cursors
__device__ __align__(16) int2 g_edge[NE];      // CSR: {src, float_bits(ew)} per slot
__device__ __align__(16) __half g_w16[4 * FD * FD];  // fp16 W
__device__ __align__(16) __half g_x16p[NN * FD];     // fp16: dis[v] * x[v]   (hop1 in)
__device__ __align__(16) __half g_x16r[NN * FD];     // fp16: x[v]            (GEMM in)
__device__ __align__(16) __half g_h1h[NN * FD];      // fp16: dis[v] * h1[v]
__device__ __align__(16) __half g_h1r[NN * FD];      // fp16: h1[v]
__device__ __align__(16) __half g_h2h[NN * FD];      // fp16: dis[v] * h2[v]
__device__ __align__(16) __half g_h2r[NN * FD];      // fp16: h2[v]
__device__ __align__(16) __half g_h3r[NN * FD];      // fp16: h3[v]
__device__ float g_out[NN * FD];
__device__ float g_sum[NG * FD];
__device__ float g_sq[NG * FD];
__device__ float g_cnt[NG];
__device__ float g_psum[NG * FD];
__device__ float g_pmax[NG * FD];   // values >= 0 so uint order == float order
__device__ float g_mc[NG * FD];     // mean * mean_scale
__device__ float g_inv[NG * FD];    // gn_weight * rsqrt(var + eps)

// -------- zero scratch --------
__global__ void k_zero() {
    int i = blockIdx.x * blockDim.x + threadIdx.x;
    if (i < NN) { g_deg[i] = 0.f; g_cntI[i] = 0; }
    if (i < NG * FD) { g_sum[i] = 0.f; g_sq[i] = 0.f; g_psum[i] = 0.f; g_pmax[i] = 0.f; }
    if (i < NG) g_cnt[i] = 0.f;
}

// -------- W -> fp16 --------
__global__ void k_w16(const float* __restrict__ W) {
    int i = blockIdx.x * blockDim.x + threadIdx.x;
    if (i >= 4 * FD * FD / 2) return;
    float2 v = ((const float2*)W)[i];
    ((__half2*)g_w16)[i] = __floats2half2_rn(v.x, v.y);
}

// -------- degree: weighted + integer count --------
__global__ void k_deg(const int* __restrict__ dst, const float* __restrict__ ew) {
    int e = blockIdx.x * blockDim.x + threadIdx.x;
    if (e >= NE) return;
    int d = dst[e];
    atomicAdd(&g_deg[d], ew[e]);
    atomicAdd(&g_cntI[d], 1);
}

// -------- x -> fp16 shadows: premultiplied (hop) and raw (GEMM) --------
__global__ void k_x16(const float* __restrict__ x) {
    int i = blockIdx.x * blockDim.x + threadIdx.x;   // one per 4 floats
    if (i >= NN * FD / 4) return;
    int node = i >> 4;                               // FD/4 = 16 chunks per node
    float dg = g_deg[node];
    float dd = (dg > 0.f) ? rsqrtf(dg) : 0.f;
    float4 v = __ldg((const float4*)x + i);
    ((__half2*)g_x16r)[i * 2]     = __floats2half2_rn(v.x, v.y);
    ((__half2*)g_x16r)[i * 2 + 1] = __floats2half2_rn(v.z, v.w);
    ((__half2*)g_x16p)[i * 2]     = __floats2half2_rn(v.x * dd, v.y * dd);
    ((__half2*)g_x16p)[i * 2 + 1] = __floats2half2_rn(v.z * dd, v.w * dd);
}

// -------- multi-block exclusive scan of g_cntI -> g_ptr / g_fill --------
__global__ void k_scan1() {
    int i = blockIdx.x * 256 + threadIdx.x;
    int v = (i < NN) ? g_cntI[i] : 0;
    __shared__ int sw[8];
    #pragma unroll
    for (int o = 16; o; o >>= 1) v += __shfl_down_sync(0xffffffffu, v, o);
    if ((threadIdx.x & 31) == 0) sw[threadIdx.x >> 5] = v;
    __syncthreads();
    if (threadIdx.x < 8) {
        int t = sw[threadIdx.x];
        #pragma unroll
        for (int o = 4; o; o >>= 1) t += __shfl_down_sync(0xffu, t, o);
        if (threadIdx.x == 0) g_bsum[blockIdx.x] = t;
    }
}
__global__ void k_scan2() {
    __shared__ int sp[512];
    int t = threadIdx.x;
    int v = (t < NB) ? g_bsum[t] : 0;
    sp[t] = v;
    __syncthreads();
    for (int off = 1; off < 512; off <<= 1) {
        int u = (t >= off) ? sp[t - off] : 0;
        __syncthreads();
        sp[t] += u;
        __syncthreads();
    }
    if (t < NB) g_bsum[t] = sp[t] - v;
    if (t == 0) g_ptr[NN] = NE;
}
__global__ void k_scan3() {
    __shared__ int sp[256];
    int i = blockIdx.x * 256 + threadIdx.x;
    int v = (i < NN) ? g_cntI[i] : 0;
    sp[threadIdx.x] = v;
    __syncthreads();
    for (int off = 1; off < 256; off <<= 1) {
        int u = (threadIdx.x >= off) ? sp[threadIdx.x - off] : 0;
        __syncthreads();
        sp[threadIdx.x] += u;
        __syncthreads();
    }
    if (i < NN) {
        int p = g_bsum[blockIdx.x] + sp[threadIdx.x] - v;
        g_ptr[i] = p;
        g_fill[i] = p;
    }
}

// -------- build CSR slots: just (src, ew) --------
__global__ void k_build(const int* __restrict__ src, const int* __restrict__ dst,
                        const float* __restrict__ ew) {
    int e = blockIdx.x * blockDim.x + threadIdx.x;
    if (e >= NE) return;
    int s = src[e], d = dst[e];
    float w = ew[e];
    int pos = atomicAdd(&g_fill[d], 1);
    g_edge[pos] = make_int2(s, __float_as_int(w));
}

// -------- gather hop (fp16 in, fp32 accumulate, dis-premultiplied) --------
__device__ __forceinline__ void hop_math(float* acc, float4 raw, float w) {
    const __half2* h2 = (const __half2*)&raw;
    #pragma unroll
    for (int q = 0; q < 4; q++) {
        float2 f = __half22float2(h2[q]);
        acc[q * 2]     += w * f.x;
        acc[q * 2 + 1] += w * f.y;
    }
}

template <bool WRITE_PRE>
__device__ __forceinline__ void hop_body(const __half* __restrict__ hin,
                                         __half* __restrict__ houtr,
                                         __half* __restrict__ houtp) {
    unsigned tid = blockIdx.x * blockDim.x + threadIdx.x;
    unsigned node = tid >> 3;
    if (node >= NN) return;
    int c = (tid & 7) * 8;
    int beg = g_ptr[node];
    int end = g_ptr[node + 1];
    float acc[8] = {0.f, 0.f, 0.f, 0.f, 0.f, 0.f, 0.f, 0.f};
    int i = beg;
    if (i < end && (i & 1)) {                    // align to even slot
        int2 m = __ldg(&g_edge[i]);
        float4 r = __ldg((const float4*)(hin + (size_t)m.x * FD + c));
        hop_math(acc, r, __int_as_float(m.y));
        i++;
    }
    for (; i + 4 <= end; i += 4) {
        int4 m0 = __ldg((const int4*)&g_edge[i]);
        int4 m1 = __ldg((const int4*)&g_edge[i + 2]);
        float4 r0 = __ldg((const float4*)(hin + (size_t)m0.x * FD + c));
        float4 r1 = __ldg((const float4*)(hin + (size_t)m0.z * FD + c));
        float4 r2 = __ldg((const float4*)(hin + (size_t)m1.x * FD + c));
        float4 r3 = __ldg((const float4*)(hin + (size_t)m1.z * FD + c));
        hop_math(acc, r0, __int_as_float(m0.y));
        hop_math(acc, r1, __int_as_float(m0.w));
        hop_math(acc, r2, __int_as_float(m1.y));
        hop_math(acc, r3, __int_as_float(m1.w));
    }
    if (i + 2 <= end) {
        int4 m = __ldg((const int4*)&g_edge[i]);
        float4 r0 = __ldg((const float4*)(hin + (size_t)m.x * FD + c));
        float4 r1 = __ldg((const float4*)(hin + (size_t)m.z * FD + c));
        hop_math(acc, r0, __int_as_float(m.y));
        hop_math(acc, r1, __int_as_float(m.w));
        i += 2;
    }
    if (i < end) {
        int2 m = __ldg(&g_edge[i]);
        float4 r = __ldg((const float4*)(hin + (size_t)m.x * FD + c));
        hop_math(acc, r, __int_as_float(m.y));
    }
    float dg = g_deg[node];
    float dd = (dg > 0.f) ? rsqrtf(dg) : 0.f;
    float h0 = dd * acc[0], h1 = dd * acc[1], h2 = dd * acc[2], h3 = dd * acc[3];
    float h4 = dd * acc[4], h5 = dd * acc[5], h6 = dd * acc[6], h7 = dd * acc[7];
    __half2 o[4];
    o[0] = __floats2half2_rn(h0, h1);
    o[1] = __floats2half2_rn(h2, h3);
    o[2] = __floats2half2_rn(h4, h5);
    o[3] = __floats2half2_rn(h6, h7);
    *(float4*)(houtr + (size_t)node * FD + c) = *(float4*)o;   // raw fp16 for GEMM
    if (WRITE_PRE) {
        __half2 p[4];
        p[0] = __floats2half2_rn(dd * h0, dd * h1);
        p[1] = __floats2half2_rn(dd * h2, dd * h3);
        p[2] = __floats2half2_rn(dd * h4, dd * h5);
        p[3] = __floats2half2_rn(dd * h6, dd * h7);
        *(float4*)(houtp + (size_t)node * FD + c) = *(float4*)p;
    }
}

__global__ void k_hop1() { hop_body<true >(g_x16p, g_h1r, g_h1h); }
__global__ void k_hop2() { hop_body<true >(g_h1h, g_h2r, g_h2h); }
__global__ void k_hop3() { hop_body<false>(g_h2h, g_h3r, nullptr); }

// -------- tensor-core GEMM: out = x@W0 + h1@W1 + h2@W2 + h3@W3 + b --------
// block = 128 thr (4 warps), tile = 64 nodes x 64 outputs.
// smem XOR-swizzled (16B chunk ^= row&7) -> conflict-free ldmatrix.
__global__ void k_gemm_tc(const float* __restrict__ b) {
    __shared__ __align__(16) __half Wsm[4 * FD * FD];   // 32 KB
    __shared__ __align__(16) __half Hsm[FD * FD];       // 8 KB

    int tid = threadIdx.x;
    int w = tid >> 5, lane = tid & 31;
    int node0 = blockIdx.x * 64;

    // load all 4 W_k into swizzled smem
    {
        const uint4* srcw = (const uint4*)g_w16;
        uint4* dstw = (uint4*)Wsm;
        #pragma unroll
        for (int t = tid; t < 2048; t += 128) {
            int hop = t >> 9;
            int row = (t >> 3) & 63;
            int c = t & 7;
            dstw[hop * 512 + row * 8 + (c ^ (row & 7))] = srcw[t];
        }
    }

    float acc[8][4];
    #pragma unroll
    for (int n = 0; n < 8; n++) { acc[n][0] = acc[n][1] = acc[n][2] = acc[n][3] = 0.f; }

    const __half* hs[4] = { g_x16r, g_h1r, g_h2r, g_h3r };

    unsigned hbase = (unsigned)__cvta_generic_to_shared(Hsm);
    unsigned wbase = (unsigned)__cvta_generic_to_shared(Wsm);

    for (int k = 0; k < 4; k++) {
        __syncthreads();   // also covers W load on first iter / Hsm reuse
        const __half* __restrict__ h = hs[k];
        #pragma unroll
        for (int t = tid; t < 512; t += 128) {
            int row = t >> 3, c = t & 7;
            int node = min(node0 + row, NN - 1);
            uint4 v = *((const uint4*)(h + (size_t)node * FD) + c);
            ((uint4*)Hsm)[row * 8 + (c ^ (row & 7))] = v;
        }
        __syncthreads();

        // A fragments for the 4 k-steps (row = w*16 + lane%16, chunk = ks*2 + lane/16)
        unsigned a[4][4];
        int arow = w * 16 + (lane & 15);
        #pragma unroll
        for (int ks = 0; ks < 4; ks++) {
            int chunk = ks * 2 + (lane >> 4);
            unsigned addr = hbase + (unsigned)((arow * 8 + (chunk ^ (arow & 7))) * 16);
            asm volatile("ldmatrix.sync.aligned.m8n8.x4.shared.b16 {%0,%1,%2,%3}, [%4];"
                         : "=r"(a[ks][0]), "=r"(a[ks][1]), "=r"(a[ks][2]), "=r"(a[ks][3])
                         : "r"(addr));
        }
        #pragma unroll
        for (int nt = 0; nt < 8; nt++) {
            #pragma unroll
            for (int ks = 0; ks < 4; ks++) {
                int brow = ks * 16 + (lane & 15);
                unsigned baddr = wbase +
                    (unsigned)((k * 512 + brow * 8 + (nt ^ (brow & 7))) * 16);
                unsigned b0, b1;
                asm volatile("ldmatrix.sync.aligned.m8n8.x2.trans.shared.b16 {%0,%1}, [%2];"
                             : "=r"(b0), "=r"(b1) : "r"(baddr));
                asm volatile("mma.sync.aligned.m16n8k16.row.col.f32.f16.f16.f32 "
                             "{%0,%1,%2,%3},{%4,%5,%6,%7},{%8,%9},{%0,%1,%2,%3};"
                             : "+f"(acc[nt][0]), "+f"(acc[nt][1]),
                               "+f"(acc[nt][2]), "+f"(acc[nt][3])
                             : "r"(a[ks][0]), "r"(a[ks][1]), "r"(a[ks][2]), "r"(a[ks][3]),
                               "r"(b0), "r"(b1));
            }
        }
    }

    // store with bias: thread owns (row0, row0+8) x cols (nt*8 + (lane%4)*2, +1)
    int r0 = node0 + w * 16 + (lane >> 2);
    int col0 = (lane & 3) * 2;
    #pragma unroll
    for (int nt = 0; nt < 8; nt++) {
        int col = nt * 8 + col0;
        float bx = __ldg(&b[col]), by = __ldg(&b[col + 1]);
        if (r0 < NN)
            *(float2*)&g_out[(size_t)r0 * FD + col] =
                make_float2(acc[nt][0] + bx, acc[nt][1] + by);
        if (r0 + 8 < NN)
            *(float2*)&g_out[(size_t)(r0 + 8) * FD + col] =
                make_float2(acc[nt][2] + bx, acc[nt][3] + by);
    }
}

// -------- per-graph sum / sumsq / count over g_out (batch sorted) --------
__global__ void k_stats(const int* __restrict__ batch) {
    int f    = threadIdx.x & 63;
    int lane = threadIdx.x >> 6;   // 0..3
    int base = blockIdx.x * 128;
    float s = 0.f, q = 0.f, c = 0.f;
    int cur = -1;
    for (int t = 0; t < 32; t++) {
        int n = base + t * 4 + lane;
        if (n >= NN) break;
        int g = batch[n];
        if (g != cur) {
            if (cur >= 0) {
                atomicAdd(&g_sum[cur * FD + f], s);
                atomicAdd(&g_sq[cur * FD + f], q);
                if (f == 0) atomicAdd(&g_cnt[cur], c);
            }
            cur = g; s = 0.f; q = 0.f; c = 0.f;
        }
        float v = g_out[n * FD + f];
        s += v; q += v * v; c += 1.f;
    }
    if (cur >= 0) {
        atomicAdd(&g_sum[cur * FD + f], s);
        atomicAdd(&g_sq[cur * FD + f], q);
        if (f == 0) atomicAdd(&g_cnt[cur], c);
    }
}

// -------- mean/var -> premultiplied center & inv-std --------
__global__ void k_meanvar(const float* __restrict__ gnw, const float* __restrict__ ms) {
    int i = blockIdx.x * blockDim.x + threadIdx.x;
    if (i >= NG * FD) return;
    int g = i >> 6, f = i & 63;
    float cnt  = fmaxf(g_cnt[g], 1.f);
    float mean = g_sum[i] / cnt;
    float m    = ms[f];
    float var = g_sq[i] / cnt - 2.f * m * mean * mean + m * m * mean * mean;
    g_mc[i]  = mean * m;
    g_inv[i] = gnw[f] * rsqrtf(var + EPSV);
}

// -------- final: h_emb = relu(gn(out) + x), accumulate pool sum/max --------
__global__ void k_final(const float* __restrict__ x, const int* __restrict__ batch,
                        const float* __restrict__ gnb, float* __restrict__ out) {
    int f    = threadIdx.x & 63;
    int lane = threadIdx.x >> 6;
    int base = blockIdx.x * 128;
    float bb = gnb[f];
    float s = 0.f, mx = 0.f, mc = 0.f, iv = 0.f;
    int cur = -1;
    for (int t = 0; t < 32; t++) {
        int n = base + t * 4 + lane;
        if (n >= NN) break;
        int g = batch[n];
        if (g != cur) {
            if (cur >= 0) {
                atomicAdd(&g_psum[cur * FD + f], s);
                atomicMax((unsigned int*)&g_pmax[cur * FD + f], __float_as_uint(mx));
            }
            cur = g; s = 0.f; mx = 0.f;
            mc = g_mc[g * FD + f];
            iv = g_inv[g * FD + f];
        }
        float v = (g_out[n * FD + f] - mc) * iv + bb + x[n * FD + f];
        v = fmaxf(v, 0.f);
        out[n * FD + f] = v;
        s += v;
        mx = fmaxf(mx, v);
    }
    if (cur >= 0) {
        atomicAdd(&g_psum[cur * FD + f], s);
        atomicMax((unsigned int*)&g_pmax[cur * FD + f], __float_as_uint(mx));
    }
}

// -------- pooled output: flat[g] = [mean_pool | max_pool] --------
__global__ void k_pool(float* __restrict__ out) {
    int i = blockIdx.x * blockDim.x + threadIdx.x;
    if (i >= NG * FD) return;
    int g = i >> 6, f = i & 63;
    float cnt = fmaxf(g_cnt[g], 1.f);
    out[NN * FD + g * 2 * FD + f]      = g_psum[i] / cnt;
    out[NN * FD + g * 2 * FD + FD + f] = g_pmax[i];
}

extern "C" void kernel_launch(void* const* d_in, const int* in_sizes, int n_in,
                              void* d_out, int out_size) {
    const float* x     = (const float*)d_in[0];
    const int*   ei    = (const int*)  d_in[1];
    const int*   batch = (const int*)  d_in[2];
    const float* ew    = (const float*)d_in[3];
    const float* W     = (const float*)d_in[4];
    const float* b     = (const float*)d_in[5];
    const float* gnw   = (const float*)d_in[6];
    const float* gnb   = (const float*)d_in[7];
    const float* ms    = (const float*)d_in[8];
    const int* src = ei;
    const int* dst = ei + NE;
    float* out = (float*)d_out;

    k_zero<<<(NN + 255) / 256, 256>>>();
    k_w16<<<(4 * FD * FD / 2 + 255) / 256, 256>>>(W);
    k_deg<<<(NE + 255) / 256, 256>>>(dst, ew);
    k_x16<<<(NN * FD / 4 + 255) / 256, 256>>>(x);   // after k_deg (needs dis)
    k_scan1<<<NB, 256>>>();
    k_scan2<<<1, 512>>>();
    k_scan3<<<NB, 256>>>();
    k_build<<<(NE + 255) / 256, 256>>>(src, dst, ew);
    k_hop1<<<(NN * 8 + 255) / 256, 256>>>();
    k_hop2<<<(NN * 8 + 255) / 256, 256>>>();
    k_hop3<<<(NN * 8 + 255) / 256, 256>>>();
    k_gemm_tc<<<(NN + 63) / 64, 128>>>(b);
    k_stats<<<(NN + 127) / 128, 256>>>(batch);
    k_meanvar<<<(NG * FD + 255) / 256, 256>>>(gnw, ms);
    k_final<<<(NN + 127) / 128, 256>>>(x, batch, gnb, out);
    k_pool<<<(NG * FD + 255) / 256, 256>>>(out);
}

// round 15
// speedup vs baseline: 2.4255x; 1.0420x over previous
#include <cuda_runtime.h>
#include <cuda_fp16.h>

#define NN 100000
#define NE 1600000
#define FD 64
#define NG 64
#define EPSV 1e-5f
#define NB ((NN + 255) / 256)   // 391 scan blocks

// -------- scratch (device globals: no allocation allowed) --------
__device__ unsigned long long g_degP[NN];      // packed: count<<48 | sum_fx32
__device__ int   g_bsum[NB];                   // per-block sums for scan
__device__ int   g_ptr[NN + 1];                // CSR row pointers (by dst)
__device__ int   g_fill[NN];                   // running fill cursors
__device__ __align__(16) int2 g_edge[NE];      // CSR: {src, float_bits(ew)} per slot
__device__ __align__(16) __half g_w16[4 * FD * FD];  // fp16 W
__device__ __align__(16) __half g_x16p[NN * FD];     // fp16: dis[v] * x[v]   (hop1 in)
__device__ __align__(16) __half g_x16r[NN * FD];     // fp16: x[v]            (GEMM in)
__device__ __align__(16) __half g_h1h[NN * FD];      // fp16: dis[v] * h1[v]
__device__ __align__(16) __half g_h2h[NN * FD];      // fp16: dis[v] * h2[v]
__device__ __align__(16) __half g_h3r[NN * FD];      // fp16: h3[v]
__device__ float g_out[NN * FD];
__device__ float g_sum[NG * FD];
__device__ float g_sq[NG * FD];
__device__ float g_cnt[NG];
__device__ float g_psum[NG * FD];
__device__ float g_pmax[NG * FD];   // values >= 0 so uint order == float order
__device__ float g_mc[NG * FD];     // mean * mean_scale
__device__ float g_inv[NG * FD];    // gn_weight * rsqrt(var + eps)

__device__ __forceinline__ float unpack_deg(unsigned long long v) {
    return (float)(v & 0xFFFFFFFFFFFFULL) * (1.0f / 4294967296.0f);
}
__device__ __forceinline__ int unpack_cnt(unsigned long long v) {
    return (int)(v >> 48);
}

// -------- zero scratch --------
__global__ void k_zero() {
    int i = blockIdx.x * blockDim.x + threadIdx.x;
    if (i < NN) g_degP[i] = 0ull;
    if (i < NG * FD) { g_sum[i] = 0.f; g_sq[i] = 0.f; g_psum[i] = 0.f; g_pmax[i] = 0.f; }
    if (i < NG) g_cnt[i] = 0.f;
}

// -------- W -> fp16 --------
__global__ void k_w16(const float* __restrict__ W) {
    int i = blockIdx.x * blockDim.x + threadIdx.x;
    if (i >= 4 * FD * FD / 2) return;
    float2 v = ((const float2*)W)[i];
    ((__half2*)g_w16)[i] = __floats2half2_rn(v.x, v.y);
}

// -------- degree: single packed 64-bit atomic per edge --------
__global__ void k_deg(const int* __restrict__ dst, const float* __restrict__ ew) {
    int e = blockIdx.x * blockDim.x + threadIdx.x;
    if (e >= NE) return;
    int d = dst[e];
    unsigned long long fx = (unsigned long long)(ew[e] * 4294967296.0f);
    atomicAdd(&g_degP[d], (1ull << 48) | fx);
}

// -------- x -> fp16 shadows: premultiplied (hop) and raw (GEMM) --------
__global__ void k_x16(const float* __restrict__ x) {
    int i = blockIdx.x * blockDim.x + threadIdx.x;   // one per 4 floats
    if (i >= NN * FD / 4) return;
    int node = i >> 4;                               // FD/4 = 16 chunks per node
    float dg = unpack_deg(g_degP[node]);
    float dd = (dg > 0.f) ? rsqrtf(dg) : 0.f;
    float4 v = __ldg((const float4*)x + i);
    ((__half2*)g_x16r)[i * 2]     = __floats2half2_rn(v.x, v.y);
    ((__half2*)g_x16r)[i * 2 + 1] = __floats2half2_rn(v.z, v.w);
    ((__half2*)g_x16p)[i * 2]     = __floats2half2_rn(v.x * dd, v.y * dd);
    ((__half2*)g_x16p)[i * 2 + 1] = __floats2half2_rn(v.z * dd, v.w * dd);
}

// -------- multi-block exclusive scan of counts -> g_ptr / g_fill --------
__global__ void k_scan1() {
    int i = blockIdx.x * 256 + threadIdx.x;
    int v = (i < NN) ? unpack_cnt(g_degP[i]) : 0;
    __shared__ int sw[8];
    #pragma unroll
    for (int o = 16; o; o >>= 1) v += __shfl_down_sync(0xffffffffu, v, o);
    if ((threadIdx.x & 31) == 0) sw[threadIdx.x >> 5] = v;
    __syncthreads();
    if (threadIdx.x < 8) {
        int t = sw[threadIdx.x];
        #pragma unroll
        for (int o = 4; o; o >>= 1) t += __shfl_down_sync(0xffu, t, o);
        if (threadIdx.x == 0) g_bsum[blockIdx.x] = t;
    }
}
__global__ void k_scan2() {
    __shared__ int sp[512];
    int t = threadIdx.x;
    int v = (t < NB) ? g_bsum[t] : 0;
    sp[t] = v;
    __syncthreads();
    for (int off = 1; off < 512; off <<= 1) {
        int u = (t >= off) ? sp[t - off] : 0;
        __syncthreads();
        sp[t] += u;
        __syncthreads();
    }
    if (t < NB) g_bsum[t] = sp[t] - v;
    if (t == 0) g_ptr[NN] = NE;
}
__global__ void k_scan3() {
    __shared__ int sp[256];
    int i = blockIdx.x * 256 + threadIdx.x;
    int v = (i < NN) ? unpack_cnt(g_degP[i]) : 0;
    sp[threadIdx.x] = v;
    __syncthreads();
    for (int off = 1; off < 256; off <<= 1) {
        int u = (threadIdx.x >= off) ? sp[threadIdx.x - off] : 0;
        __syncthreads();
        sp[threadIdx.x] += u;
        __syncthreads();
    }
    if (i < NN) {
        int p = g_bsum[blockIdx.x] + sp[threadIdx.x] - v;
        g_ptr[i] = p;
        g_fill[i] = p;
    }
}

// -------- build CSR slots: 2 edges/thread, vector index loads --------
__global__ void k_build(const int* __restrict__ src, const int* __restrict__ dst,
                        const float* __restrict__ ew) {
    int t = blockIdx.x * blockDim.x + threadIdx.x;
    if (t >= NE / 2) return;
    int2   s2 = ((const int2*)src)[t];
    int2   d2 = ((const int2*)dst)[t];
    float2 w2 = ((const float2*)ew)[t];
    int p0 = atomicAdd(&g_fill[d2.x], 1);
    g_edge[p0] = make_int2(s2.x, __float_as_int(w2.x));
    int p1 = atomicAdd(&g_fill[d2.y], 1);
    g_edge[p1] = make_int2(s2.y, __float_as_int(w2.y));
}

// -------- gather hop (fp16 in, fp32 accumulate, dis-premultiplied) --------
__device__ __forceinline__ void hop_math(float* acc, float4 raw, float w) {
    const __half2* h2 = (const __half2*)&raw;
    #pragma unroll
    for (int q = 0; q < 4; q++) {
        float2 f = __half22float2(h2[q]);
        acc[q * 2]     += w * f.x;
        acc[q * 2 + 1] += w * f.y;
    }
}

// PRE_OUT: store dis*h (for next hop). else store raw h (for GEMM).
template <bool PRE_OUT>
__device__ __forceinline__ void hop_body(const __half* __restrict__ hin,
                                         __half* __restrict__ hout) {
    unsigned tid = blockIdx.x * blockDim.x + threadIdx.x;
    unsigned node = tid >> 3;
    if (node >= NN) return;
    int c = (tid & 7) * 8;
    int beg = g_ptr[node];
    int end = g_ptr[node + 1];
    float acc[8] = {0.f, 0.f, 0.f, 0.f, 0.f, 0.f, 0.f, 0.f};
    int i = beg;
    if (i < end && (i & 1)) {                    // align to even slot
        int2 m = __ldg(&g_edge[i]);
        float4 r = __ldg((const float4*)(hin + (size_t)m.x * FD + c));
        hop_math(acc, r, __int_as_float(m.y));
        i++;
    }
    for (; i + 4 <= end; i += 4) {
        int4 m0 = __ldg((const int4*)&g_edge[i]);
        int4 m1 = __ldg((const int4*)&g_edge[i + 2]);
        float4 r0 = __ldg((const float4*)(hin + (size_t)m0.x * FD + c));
        float4 r1 = __ldg((const float4*)(hin + (size_t)m0.z * FD + c));
        float4 r2 = __ldg((const float4*)(hin + (size_t)m1.x * FD + c));
        float4 r3 = __ldg((const float4*)(hin + (size_t)m1.z * FD + c));
        hop_math(acc, r0, __int_as_float(m0.y));
        hop_math(acc, r1, __int_as_float(m0.w));
        hop_math(acc, r2, __int_as_float(m1.y));
        hop_math(acc, r3, __int_as_float(m1.w));
    }
    if (i + 2 <= end) {
        int4 m = __ldg((const int4*)&g_edge[i]);
        float4 r0 = __ldg((const float4*)(hin + (size_t)m.x * FD + c));
        float4 r1 = __ldg((const float4*)(hin + (size_t)m.z * FD + c));
        hop_math(acc, r0, __int_as_float(m.y));
        hop_math(acc, r1, __int_as_float(m.w));
        i += 2;
    }
    if (i < end) {
        int2 m = __ldg(&g_edge[i]);
        float4 r = __ldg((const float4*)(hin + (size_t)m.x * FD + c));
        hop_math(acc, r, __int_as_float(m.y));
    }
    float dg = unpack_deg(g_degP[node]);
    float dd = (dg > 0.f) ? rsqrtf(dg) : 0.f;
    float s = PRE_OUT ? (dd * dd) : dd;          // pre: dis*(dis*acc); raw: dis*acc
    __half2 o[4];
    o[0] = __floats2half2_rn(s * acc[0], s * acc[1]);
    o[1] = __floats2half2_rn(s * acc[2], s * acc[3]);
    o[2] = __floats2half2_rn(s * acc[4], s * acc[5]);
    o[3] = __floats2half2_rn(s * acc[6], s * acc[7]);
    *(float4*)(hout + (size_t)node * FD + c) = *(float4*)o;
}

__global__ void k_hop1() { hop_body<true >(g_x16p, g_h1h); }
__global__ void k_hop2() { hop_body<true >(g_h1h, g_h2h); }
__global__ void k_hop3() { hop_body<false>(g_h2h, g_h3r); }

// -------- tensor-core GEMM: out = x@W0 + h1@W1 + h2@W2 + h3@W3 + b --------
// h1/h2 reconstructed from premultiplied shadows: h_raw = h_pre * sqrt(deg).
__global__ void k_gemm_tc(const float* __restrict__ b) {
    __shared__ __align__(16) __half Wsm[4 * FD * FD];   // 32 KB
    __shared__ __align__(16) __half Hsm[FD * FD];       // 8 KB

    int tid = threadIdx.x;
    int w = tid >> 5, lane = tid & 31;
    int node0 = blockIdx.x * 64;

    // load all 4 W_k into swizzled smem
    {
        const uint4* srcw = (const uint4*)g_w16;
        uint4* dstw = (uint4*)Wsm;
        #pragma unroll
        for (int t = tid; t < 2048; t += 128) {
            int hop = t >> 9;
            int row = (t >> 3) & 63;
            int c = t & 7;
            dstw[hop * 512 + row * 8 + (c ^ (row & 7))] = srcw[t];
        }
    }

    float acc[8][4];
    #pragma unroll
    for (int n = 0; n < 8; n++) { acc[n][0] = acc[n][1] = acc[n][2] = acc[n][3] = 0.f; }

    const __half* hs[4] = { g_x16r, g_h1h, g_h2h, g_h3r };

    unsigned hbase = (unsigned)__cvta_generic_to_shared(Hsm);
    unsigned wbase = (unsigned)__cvta_generic_to_shared(Wsm);

    for (int k = 0; k < 4; k++) {
        __syncthreads();   // also covers W load on first iter / Hsm reuse
        const __half* __restrict__ h = hs[k];
        bool rescale = (k == 1) || (k == 2);
        #pragma unroll
        for (int t = tid; t < 512; t += 128) {
            int row = t >> 3, c = t & 7;
            int node = min(node0 + row, NN - 1);
            uint4 v = *((const uint4*)(h + (size_t)node * FD) + c);
            if (rescale) {
                float sd = sqrtf(unpack_deg(g_degP[node]));
                __half2* hv = (__half2*)&v;
                #pragma unroll
                for (int q = 0; q < 4; q++) {
                    float2 f = __half22float2(hv[q]);
                    hv[q] = __floats2half2_rn(f.x * sd, f.y * sd);
                }
            }
            ((uint4*)Hsm)[row * 8 + (c ^ (row & 7))] = v;
        }
        __syncthreads();

        // A fragments for the 4 k-steps (row = w*16 + lane%16, chunk = ks*2 + lane/16)
        unsigned a[4][4];
        int arow = w * 16 + (lane & 15);
        #pragma unroll
        for (int ks = 0; ks < 4; ks++) {
            int chunk = ks * 2 + (lane >> 4);
            unsigned addr = hbase + (unsigned)((arow * 8 + (chunk ^ (arow & 7))) * 16);
            asm volatile("ldmatrix.sync.aligned.m8n8.x4.shared.b16 {%0,%1,%2,%3}, [%4];"
                         : "=r"(a[ks][0]), "=r"(a[ks][1]), "=r"(a[ks][2]), "=r"(a[ks][3])
                         : "r"(addr));
        }
        #pragma unroll
        for (int nt = 0; nt < 8; nt++) {
            #pragma unroll
            for (int ks = 0; ks < 4; ks++) {
                int brow = ks * 16 + (lane & 15);
                unsigned baddr = wbase +
                    (unsigned)((k * 512 + brow * 8 + (nt ^ (brow & 7))) * 16);
                unsigned b0, b1;
                asm volatile("ldmatrix.sync.aligned.m8n8.x2.trans.shared.b16 {%0,%1}, [%2];"
                             : "=r"(b0), "=r"(b1) : "r"(baddr));
                asm volatile("mma.sync.aligned.m16n8k16.row.col.f32.f16.f16.f32 "
                             "{%0,%1,%2,%3},{%4,%5,%6,%7},{%8,%9},{%0,%1,%2,%3};"
                             : "+f"(acc[nt][0]), "+f"(acc[nt][1]),
                               "+f"(acc[nt][2]), "+f"(acc[nt][3])
                             : "r"(a[ks][0]), "r"(a[ks][1]), "r"(a[ks][2]), "r"(a[ks][3]),
                               "r"(b0), "r"(b1));
            }
        }
    }

    // store with bias: thread owns (row0, row0+8) x cols (nt*8 + (lane%4)*2, +1)
    int r0 = node0 + w * 16 + (lane >> 2);
    int col0 = (lane & 3) * 2;
    #pragma unroll
    for (int nt = 0; nt < 8; nt++) {
        int col = nt * 8 + col0;
        float bx = __ldg(&b[col]), by = __ldg(&b[col + 1]);
        if (r0 < NN)
            *(float2*)&g_out[(size_t)r0 * FD + col] =
                make_float2(acc[nt][0] + bx, acc[nt][1] + by);
        if (r0 + 8 < NN)
            *(float2*)&g_out[(size_t)(r0 + 8) * FD + col] =
                make_float2(acc[nt][2] + bx, acc[nt][3] + by);
    }
}

// -------- per-graph sum / sumsq / count over g_out (batch sorted) --------
__global__ void k_stats(const int* __restrict__ batch) {
    int f    = threadIdx.x & 63;
    int lane = threadIdx.x >> 6;   // 0..3
    int base = blockIdx.x * 128;
    float s = 0.f, q = 0.f, c = 0.f;
    int cur = -1;
    for (int t = 0; t < 32; t++) {
        int n = base + t * 4 + lane;
        if (n >= NN) break;
        int g = batch[n];
        if (g != cur) {
            if (cur >= 0) {
                atomicAdd(&g_sum[cur * FD + f], s);
                atomicAdd(&g_sq[cur * FD + f], q);
                if (f == 0) atomicAdd(&g_cnt[cur], c);
            }
            cur = g; s = 0.f; q = 0.f; c = 0.f;
        }
        float v = g_out[n * FD + f];
        s += v; q += v * v; c += 1.f;
    }
    if (cur >= 0) {
        atomicAdd(&g_sum[cur * FD + f], s);
        atomicAdd(&g_sq[cur * FD + f], q);
        if (f == 0) atomicAdd(&g_cnt[cur], c);
    }
}

// -------- mean/var -> premultiplied center & inv-std --------
__global__ void k_meanvar(const float* __restrict__ gnw, const float* __restrict__ ms) {
    int i = blockIdx.x * blockDim.x + threadIdx.x;
    if (i >= NG * FD) return;
    int g = i >> 6, f = i & 63;
    float cnt  = fmaxf(g_cnt[g], 1.f);
    float mean = g_sum[i] / cnt;
    float m    = ms[f];
    float var = g_sq[i] / cnt - 2.f * m * mean * mean + m * m * mean * mean;
    g_mc[i]  = mean * m;
    g_inv[i] = gnw[f] * rsqrtf(var + EPSV);
}

// -------- final: h_emb = relu(gn(out) + x), accumulate pool sum/max --------
__global__ void k_final(const float* __restrict__ x, const int* __restrict__ batch,
                        const float* __restrict__ gnb, float* __restrict__ out) {
    int f    = threadIdx.x & 63;
    int lane = threadIdx.x >> 6;
    int base = blockIdx.x * 128;
    float bb = gnb[f];
    float s = 0.f, mx = 0.f, mc = 0.f, iv = 0.f;
    int cur = -1;
    for (int t = 0; t < 32; t++) {
        int n = base + t * 4 + lane;
        if (n >= NN) break;
        int g = batch[n];
        if (g != cur) {
            if (cur >= 0) {
                atomicAdd(&g_psum[cur * FD + f], s);
                atomicMax((unsigned int*)&g_pmax[cur * FD + f], __float_as_uint(mx));
            }
            cur = g; s = 0.f; mx = 0.f;
            mc = g_mc[g * FD + f];
            iv = g_inv[g * FD + f];
        }
        float v = (g_out[n * FD + f] - mc) * iv + bb + x[n * FD + f];
        v = fmaxf(v, 0.f);
        out[n * FD + f] = v;
        s += v;
        mx = fmaxf(mx, v);
    }
    if (cur >= 0) {
        atomicAdd(&g_psum[cur * FD + f], s);
        atomicMax((unsigned int*)&g_pmax[cur * FD + f], __float_as_uint(mx));
    }
}

// -------- pooled output: flat[g] = [mean_pool | max_pool] --------
__global__ void k_pool(float* __restrict__ out) {
    int i = blockIdx.x * blockDim.x + threadIdx.x;
    if (i >= NG * FD) return;
    int g = i >> 6, f = i & 63;
    float cnt = fmaxf(g_cnt[g], 1.f);
    out[NN * FD + g * 2 * FD + f]      = g_psum[i] / cnt;
    out[NN * FD + g * 2 * FD + FD + f] = g_pmax[i];
}

extern "C" void kernel_launch(void* const* d_in, const int* in_sizes, int n_in,
                              void* d_out, int out_size) {
    const float* x     = (const float*)d_in[0];
    const int*   ei    = (const int*)  d_in[1];
    const int*   batch = (const int*)  d_in[2];
    const float* ew    = (const float*)d_in[3];
    const float* W     = (const float*)d_in[4];
    const float* b     = (const float*)d_in[5];
    const float* gnw   = (const float*)d_in[6];
    const float* gnb   = (const float*)d_in[7];
    const float* ms    = (const float*)d_in[8];
    const int* src = ei;
    const int* dst = ei + NE;
    float* out = (float*)d_out;

    k_zero<<<(NN + 255) / 256, 256>>>();
    k_w16<<<(4 * FD * FD / 2 + 255) / 256, 256>>>(W);
    k_deg<<<(NE + 255) / 256, 256>>>(dst, ew);
    k_x16<<<(NN * FD / 4 + 255) / 256, 256>>>(x);   // after k_deg (needs dis)
    k_scan1<<<NB, 256>>>();
    k_scan2<<<1, 512>>>();
    k_scan3<<<NB, 256>>>();
    k_build<<<(NE / 2 + 255) / 256, 256>>>(src, dst, ew);
    k_hop1<<<(NN * 8 + 255) / 256, 256>>>();
    k_hop2<<<(NN * 8 + 255) / 256, 256>>>();
    k_hop3<<<(NN * 8 + 255) / 256, 256>>>();
    k_gemm_tc<<<(NN + 63) / 64, 128>>>(b);
    k_stats<<<(NN + 127) / 128, 256>>>(batch);
    k_meanvar<<<(NG * FD + 255) / 256, 256>>>(gnw, ms);
    k_final<<<(NN + 127) / 128, 256>>>(x, batch, gnb, out);
    k_pool<<<(NG * FD + 255) / 256, 256>>>(out);
}